// round 5
// baseline (speedup 1.0000x reference)
#include <cuda_runtime.h>
#include <math.h>

typedef unsigned long long u64;

#define T 512
#define GP 8
#define NB   16
#define NPQ  45
#define NPP  2025
#define NTOT 32400
#define NBLK (NTOT/GP)      /* 4050 CTAs */

/* float offsets in dynamic smem */
#define OFF_RS    0         /* 6936  : resized planar [3][8*289] (17x17 pad)     */
#define OFF_ACT1  6936      /* 20736 : act1 [32][8*81]; reused w3/wd/cx/reduce   */
#define OFF_ACT2  27672     /* 12800 : act2 [64][8*25] (5x5 pad); reused reduce2 */
#define OFF_ACT3  40472     /* 4096  : [p][512]                                  */
#define OFF_RAW   44568     /* 1536  : [3][8][64]                                */
#define OFF_W2S   46104     /* 4096  : w2 tap double buffer                      */
#define OFF_W1    50200     /* 864                                               */
#define OFF_V     51064     /* 512   : [p][64]                                   */
#define OFF_B     51576     /* 288   : b1 b2 b3 bd                               */
#define OFF_CW    51864     /* 128                                               */
#define OFF_VN2   51992     /* 8                                                 */
#define SMEM_FLOATS 52000
#define SMEM_BYTES  (SMEM_FLOATS * 4)

__device__ float g_ysum[NB * 128];

/* ---- packed fp32x2 ---- */
__device__ __forceinline__ u64 pack2(float lo, float hi) {
    u64 r; asm("mov.b64 %0, {%1, %2};" : "=l"(r) : "f"(lo), "f"(hi)); return r;
}
__device__ __forceinline__ void unpack2(u64 v, float& lo, float& hi) {
    asm("mov.b64 {%0, %1}, %2;" : "=f"(lo), "=f"(hi) : "l"(v));
}
__device__ __forceinline__ void fma2(u64& d, u64 a, u64 b) {
    asm("fma.rn.f32x2 %0, %1, %2, %0;" : "+l"(d) : "l"(a), "l"(b));
}

__device__ __forceinline__ void cp16(float* dst, const float* src) {
    unsigned s = (unsigned)__cvta_generic_to_shared(dst);
    asm volatile("cp.async.cg.shared.global [%0], [%1], 16;\n" :: "r"(s), "l"(src));
}
__device__ __forceinline__ void cp_commit() { asm volatile("cp.async.commit_group;\n"); }
__device__ __forceinline__ void cp_wait0()  { asm volatile("cp.async.wait_group 0;\n"); }

/* jax.image.resize 'linear' 8->16 */
__device__ __forceinline__ void rtab(int i, int& a0, int& a1, float& w0, float& w1) {
    if (i == 0)       { a0 = 0; a1 = 0; w0 = 1.f;   w1 = 0.f;   }
    else if (i == 15) { a0 = 7; a1 = 7; w0 = 1.f;   w1 = 0.f;   }
    else if (i & 1)   { int m = i >> 1; a0 = m;     a1 = m + 1; w0 = 0.75f; w1 = 0.25f; }
    else              { int m = i >> 1; a0 = m - 1; a1 = m;     w0 = 0.25f; w1 = 0.75f; }
}

__global__ __launch_bounds__(T, 1)
void main_kernel(const float* __restrict__ images,
                 const float* __restrict__ w1, const float* __restrict__ b1,
                 const float* __restrict__ w2, const float* __restrict__ b2,
                 const float* __restrict__ w3, const float* __restrict__ b3,
                 const float* __restrict__ wd, const float* __restrict__ bd,
                 const float* __restrict__ c_x, const float* __restrict__ comp_w,
                 const float* __restrict__ sigma)
{
    extern __shared__ float sm[];
    const int tid = threadIdx.x;
    const int g0  = blockIdx.x * GP;
    float* s_b  = sm + OFF_B;
    float* s_cw = sm + OFF_CW;

    /* ---- init ---- */
    for (int i = tid; i < 864; i += T) sm[OFF_W1 + i] = w1[i];
    if (tid < 32)  s_b[tid]       = b1[tid];
    if (tid < 64)  s_b[32 + tid]  = b2[tid];
    if (tid < 128) s_b[96 + tid]  = b3[tid];
    if (tid < 64)  s_b[224 + tid] = bd[tid];
    if (tid < 128) s_cw[tid]      = comp_w[tid];
    for (int i = tid; i < OFF_ACT3 / 4; i += T)
        ((float4*)sm)[i] = make_float4(0.f, 0.f, 0.f, 0.f);

    for (int i = tid; i < 1536; i += T) {
        int c = i >> 9, rem = i & 511, p = rem >> 6, r = rem & 63;
        int iy = r >> 3, ix = r & 7;
        int g = g0 + p, b = g / NPP, pp = g % NPP;
        int py = pp / NPQ, px = pp % NPQ;
        sm[OFF_RAW + i] = images[((b * 96 + py * 2 + iy) * 96 + px * 2 + ix) * 3 + c];
    }
    __syncthreads();

    /* ---- resize 8x8 -> 16x16 into [c][p][289] ---- */
    for (int i = tid; i < 6144; i += T) {
        int c = i >> 11, rem = i & 2047, p = rem >> 8, r = rem & 255;
        int oy = r >> 4, ox = r & 15;
        int ay0, ay1, ax0, ax1; float wy0, wy1, wx0, wx1;
        rtab(oy, ay0, ay1, wy0, wy1);
        rtab(ox, ax0, ax1, wx0, wx1);
        const float* rp = sm + OFF_RAW + c * 512 + p * 64;
        float v00 = rp[ay0 * 8 + ax0], v01 = rp[ay0 * 8 + ax1];
        float v10 = rp[ay1 * 8 + ax0], v11 = rp[ay1 * 8 + ax1];
        sm[OFF_RS + c * 2312 + p * 289 + oy * 17 + ox] =
            wy0 * (wx0 * v00 + wx1 * v01) + wy1 * (wx0 * v10 + wx1 * v11);
    }
    __syncthreads();

    /* ---- conv1: M=512(8p*8oy*8ox) N=32 K=27; TM=8(ox) TN=4 ---- */
    {
        const int mt = tid >> 3, ng = tid & 7;
        const int p = mt >> 3, oy = mt & 7;
        u64 acc[8][2];
        #pragma unroll
        for (int i = 0; i < 8; i++) { acc[i][0] = 0ull; acc[i][1] = 0ull; }

        #pragma unroll 1
        for (int t = 0; t < 9; t++) {
            int ky = t / 3, kx = t - ky * 3;
            #pragma unroll
            for (int c = 0; c < 3; c++) {
                const float* ap = sm + OFF_RS + c * 2312 + p * 289 + (2 * oy + ky) * 17 + kx;
                u64 aa[8];
                #pragma unroll
                for (int i = 0; i < 8; i++) { float a = ap[2 * i]; aa[i] = pack2(a, a); }
                const u64* wp = (const u64*)(sm + OFF_W1 + (t * 3 + c) * 32 + ng * 4);
                u64 b0 = wp[0], b1v = wp[1];
                #pragma unroll
                for (int i = 0; i < 8; i++) { fma2(acc[i][0], aa[i], b0); fma2(acc[i][1], aa[i], b1v); }
            }
        }
        #pragma unroll
        for (int j = 0; j < 2; j++) {
            int oc0 = ng * 4 + 2 * j;
            float bi0 = s_b[oc0], bi1 = s_b[oc0 + 1];
            float* o0 = sm + OFF_ACT1 + oc0 * 648 + p * 81 + oy * 9;
            float* o1 = o0 + 648;
            #pragma unroll
            for (int i = 0; i < 8; i++) {
                float lo, hi; unpack2(acc[i][j], lo, hi);
                o0[i] = fmaxf(lo + bi0, 0.f);
                o1[i] = fmaxf(hi + bi1, 0.f);
            }
        }
    }
    __syncthreads();

    /* ---- conv2: M=128(8p*4oy*4ox) N=64 K=288; TM=2(ox) TN=8 ---- */
    {
        const int mt = tid >> 3, ng = tid & 7;
        const int p = mt >> 3, r = mt & 7, oy = r >> 1, oxp = r & 1;
        u64 acc[2][4];
        #pragma unroll
        for (int i = 0; i < 2; i++)
            #pragma unroll
            for (int j = 0; j < 4; j++) acc[i][j] = 0ull;

        cp16(sm + OFF_W2S + tid * 4, w2 + tid * 4);
        cp_commit();

        #pragma unroll 1
        for (int t = 0; t < 9; t++) {
            cp_wait0();
            __syncthreads();
            if (t < 8) {
                cp16(sm + OFF_W2S + ((t + 1) & 1) * 2048 + tid * 4, w2 + (t + 1) * 2048 + tid * 4);
                cp_commit();
            }
            int ky = t / 3, kx = t - ky * 3;
            const float* wb = sm + OFF_W2S + (t & 1) * 2048;
            const float* ap = sm + OFF_ACT1 + p * 81 + (2 * oy + ky) * 9 + kx + 4 * oxp;
            #pragma unroll 8
            for (int ic = 0; ic < 32; ic++) {
                float a0 = ap[ic * 648], a1 = ap[ic * 648 + 2];
                u64 aa0 = pack2(a0, a0), aa1 = pack2(a1, a1);
                const u64* wp = (const u64*)(wb + ic * 64 + ng * 8);
                u64 b0 = wp[0], b1v = wp[1], b2v = wp[2], b3v = wp[3];
                fma2(acc[0][0], aa0, b0);  fma2(acc[1][0], aa1, b0);
                fma2(acc[0][1], aa0, b1v); fma2(acc[1][1], aa1, b1v);
                fma2(acc[0][2], aa0, b2v); fma2(acc[1][2], aa1, b2v);
                fma2(acc[0][3], aa0, b3v); fma2(acc[1][3], aa1, b3v);
            }
        }
        #pragma unroll
        for (int j = 0; j < 4; j++) {
            int oc0 = ng * 8 + 2 * j;
            float bi0 = s_b[32 + oc0], bi1 = s_b[32 + oc0 + 1];
            float* o0 = sm + OFF_ACT2 + oc0 * 200 + p * 25 + oy * 5 + oxp * 2;
            float* o1 = o0 + 200;
            #pragma unroll
            for (int i = 0; i < 2; i++) {
                float lo, hi; unpack2(acc[i][j], lo, hi);
                o0[i] = fmaxf(lo + bi0, 0.f);
                o1[i] = fmaxf(hi + bi1, 0.f);
            }
        }
    }
    __syncthreads();

    /* ---- conv3: M=32(8p*4px) N=128 K=576 (pruned); ic-split by 2, TN=4 ---- */
    {
        const int ich = tid >> 8, t256 = tid & 255;
        const int p = t256 >> 5, ng = t256 & 31;
        u64 acc[4][2];
        #pragma unroll
        for (int i = 0; i < 4; i++) { acc[i][0] = 0ull; acc[i][1] = 0ull; }

        #pragma unroll
        for (int j = 0; j < 4; j++)
            cp16(sm + OFF_ACT1 + tid * 16 + j * 4, w3 + tid * 16 + j * 4);
        cp_commit();

        #pragma unroll
        for (int t = 0; t < 9; t++) {
            cp_wait0();
            __syncthreads();
            if (t < 8) {
                #pragma unroll
                for (int j = 0; j < 4; j++)
                    cp16(sm + OFF_ACT1 + ((t + 1) & 1) * 8192 + tid * 16 + j * 4,
                         w3 + (t + 1) * 8192 + tid * 16 + j * 4);
                cp_commit();
            }
            const int ky = t / 3, kx = t % 3;
            const float* wb = sm + OFF_ACT1 + (t & 1) * 8192;
            const float* ap = sm + OFF_ACT2 + p * 25;
            #pragma unroll 4
            for (int ic = 0; ic < 32; ic++) {
                const int icg = (ich << 5) + ic;
                const u64* wp = (const u64*)(wb + icg * 128 + ng * 4);
                u64 b0 = wp[0], b1v = wp[1];
                #pragma unroll
                for (int px = 0; px < 4; px++) {
                    const int iy = 2 * (px >> 1) + ky, ix = 2 * (px & 1) + kx;
                    if (iy < 4 && ix < 4) {
                        float a = ap[icg * 200 + iy * 5 + ix];
                        u64 aa = pack2(a, a);
                        fma2(acc[px][0], aa, b0);
                        fma2(acc[px][1], aa, b1v);
                    }
                }
            }
        }
        __syncthreads();
        float* buf = sm + OFF_ACT1 + tid * 17;
        #pragma unroll
        for (int px = 0; px < 4; px++)
            #pragma unroll
            for (int j = 0; j < 2; j++) {
                float lo, hi; unpack2(acc[px][j], lo, hi);
                buf[px * 4 + 2 * j]     = lo;
                buf[px * 4 + 2 * j + 1] = hi;
            }
        __syncthreads();
        if (ich == 0) {
            const float* pb = sm + OFF_ACT1 + (tid + 256) * 17;
            #pragma unroll
            for (int px = 0; px < 4; px++)
                #pragma unroll
                for (int j = 0; j < 2; j++) {
                    int oc0 = ng * 4 + 2 * j;
                    float lo, hi; unpack2(acc[px][j], lo, hi);
                    lo += pb[px * 4 + 2 * j];
                    hi += pb[px * 4 + 2 * j + 1];
                    sm[OFF_ACT3 + p * 512 + px * 128 + oc0]     = fmaxf(lo + s_b[96 + oc0], 0.f);
                    sm[OFF_ACT3 + p * 512 + px * 128 + oc0 + 1] = fmaxf(hi + s_b[96 + oc0 + 1], 0.f);
                }
        }
    }
    __syncthreads();

    /* ---- dense 512->64, K-split by 2; wd staged 2 chunks/step dbl-buffered ---- */
    {
        const int kh = tid >> 8, t256 = tid & 255;
        const int p = t256 >> 5, lane = t256 & 31, e0 = lane * 2;
        u64 accp = 0ull;

        #pragma unroll
        for (int j = 0; j < 4; j++) {
            int idx = tid * 16 + j * 4;             /* 0..8191 */
            int c = idx >> 12;                      /* half 0 -> chunk 0, half 1 -> chunk 4 */
            cp16(sm + OFF_ACT1 + idx, wd + c * 4 * 4096 + (idx & 4095));
        }
        cp_commit();

        #pragma unroll 1
        for (int s = 0; s < 4; s++) {
            cp_wait0();
            __syncthreads();
            if (s < 3) {
                #pragma unroll
                for (int j = 0; j < 4; j++) {
                    int idx = tid * 16 + j * 4;
                    int c = idx >> 12;
                    cp16(sm + OFF_ACT1 + ((s + 1) & 1) * 8192 + idx,
                         wd + (c * 4 + s + 1) * 4096 + (idx & 4095));
                }
                cp_commit();
            }
            const float* xp = sm + OFF_ACT3 + p * 512 + (kh * 4 + s) * 64;
            const float* wp = sm + OFF_ACT1 + (s & 1) * 8192 + kh * 4096;
            #pragma unroll 8
            for (int k = 0; k < 64; k++) {
                float x = xp[k];
                u64 xx = pack2(x, x);
                u64 ww = *(const u64*)(wp + k * 64 + e0);
                fma2(accp, xx, ww);
            }
        }
        __syncthreads();
        if (kh == 1) {
            float lo, hi; unpack2(accp, lo, hi);
            sm[OFF_ACT2 + t256 * 2]     = lo;
            sm[OFF_ACT2 + t256 * 2 + 1] = hi;
        }
        __syncthreads();
        if (kh == 0) {
            float lo, hi; unpack2(accp, lo, hi);
            lo += sm[OFF_ACT2 + t256 * 2];
            hi += sm[OFF_ACT2 + t256 * 2 + 1];
            sm[OFF_V + p * 64 + e0]     = lo + s_b[224 + e0];
            sm[OFF_V + p * 64 + e0 + 1] = hi + s_b[224 + e0 + 1];
        }
    }
    __syncthreads();

    /* ---- vn2 + stage c_x (stride 65) ---- */
    if (tid < GP) {
        float a = 0.f;
        const float* vp = sm + OFF_V + tid * 64;
        #pragma unroll 8
        for (int e = 0; e < 64; e++) a = fmaf(vp[e], vp[e], a);
        sm[OFF_VN2 + tid] = a;
    }
    for (int i = tid; i < 8192; i += T) {
        int k = i >> 6, e = i & 63;
        sm[OFF_ACT1 + k * 65 + e] = c_x[i];
    }
    __syncthreads();

    /* ---- head: 128 k x 4 pgroups x 2 patches ---- */
    {
        float inv_s2 = 1.f / (sigma[0] * sigma[0]);
        const int k = tid & 127, pg = tid >> 7;
        const int p0 = pg * 2;
        u64 d = pack2(sm[OFF_VN2 + p0], sm[OFF_VN2 + p0 + 1]);
        const u64 neg2 = pack2(-2.f, -2.f);
        const float* ck = sm + OFF_ACT1 + k * 65;
        const float* v0 = sm + OFF_V + p0 * 64;
        #pragma unroll 8
        for (int e = 0; e < 64; e++) {
            float cv = ck[e];
            u64 cc = pack2(cv, cv);
            u64 vv = pack2(v0[e], v0[64 + e]);
            u64 tt = cc;
            fma2(tt, neg2, vv);
            fma2(d, cc, tt);
        }
        float d0, d1; unpack2(d, d0, d1);
        float cwk = s_cw[k];
        float ow0 = fmaxf(cwk * expf(-fmaxf(d0, 0.f) * inv_s2), 1e-10f);
        float ow1 = fmaxf(cwk * expf(-fmaxf(d1, 0.f) * inv_s2), 1e-10f);
        int b0 = (g0 + p0) / NPP, b1i = (g0 + p0 + 1) / NPP;
        if (b0 == b1i) {
            atomicAdd(&g_ysum[b0 * 128 + k], ow0 + ow1);
        } else {
            atomicAdd(&g_ysum[b0 * 128 + k], ow0);
            atomicAdd(&g_ysum[b1i * 128 + k], ow1);
        }
    }
}

/* ========== fin: normalize + project; self-zeroes g_ysum for replay ========== */
__global__ void fin_kernel(const float* __restrict__ c_y, float* __restrict__ out) {
    __shared__ float s_y[NB * 128];
    __shared__ float yv2[128 * 10];
    __shared__ float rsum[NB];
    int tid = threadIdx.x;
    for (int i = tid; i < NB * 128; i += blockDim.x) {
        s_y[i] = g_ysum[i];
        g_ysum[i] = 0.f;
    }
    __syncthreads();
    for (int k = tid; k < 128; k += blockDim.x) {
        float n2 = 0.f;
        for (int i = 0; i < 10; i++) { float c = c_y[k * 10 + i]; n2 = fmaf(c, c, n2); }
        float inv = 1.f / n2;
        for (int i = 0; i < 10; i++) { float c = c_y[k * 10 + i]; yv2[k * 10 + i] = c * c * inv; }
    }
    if (tid < NB) {
        float s = 0.f;
        for (int k = 0; k < 128; k++) s += s_y[tid * 128 + k];
        rsum[tid] = s;
    }
    __syncthreads();
    if (tid < NB * 10) {
        int b = tid / 10, i = tid % 10;
        float a = 0.f;
        for (int k = 0; k < 128; k++) a = fmaf(s_y[b * 128 + k], yv2[k * 10 + i], a);
        out[tid] = a / rsum[b];
    }
}

extern "C" void kernel_launch(void* const* d_in, const int* in_sizes, int n_in,
                              void* d_out, int out_size) {
    (void)in_sizes; (void)n_in; (void)out_size;
    const float* images = (const float*)d_in[0];
    const float* w1     = (const float*)d_in[1];
    const float* b1     = (const float*)d_in[2];
    const float* w2     = (const float*)d_in[3];
    const float* b2     = (const float*)d_in[4];
    const float* w3     = (const float*)d_in[5];
    const float* b3     = (const float*)d_in[6];
    const float* wd     = (const float*)d_in[7];
    const float* bd     = (const float*)d_in[8];
    const float* c_x    = (const float*)d_in[9];
    const float* c_y    = (const float*)d_in[10];
    const float* comp_w = (const float*)d_in[11];
    const float* sigma  = (const float*)d_in[12];
    float* out = (float*)d_out;

    cudaFuncSetAttribute(main_kernel, cudaFuncAttributeMaxDynamicSharedMemorySize, SMEM_BYTES);

    main_kernel<<<NBLK, T, SMEM_BYTES>>>(images, w1, b1, w2, b2, w3, b3,
                                         wd, bd, c_x, comp_w, sigma);
    fin_kernel<<<1, 256>>>(c_y, out);
}

// round 6
// speedup vs baseline: 1.3368x; 1.3368x over previous
#include <cuda_runtime.h>
#include <math.h>

typedef unsigned long long u64;

#define T 256
#define GP 8
#define NB   16
#define NPQ  45
#define NPP  (NPQ*NPQ)
#define NTOT (NB*NPP)
#define NBLK (NTOT/GP)      /* 4050 CTAs */

/* float offsets in dynamic smem */
#define OFF_RS    0         /* 6936  : resized, planar [3][8*289] (17x17 pad)   */
#define OFF_ACT1  6936      /* 20736 : [32][8*81] (9x9 pad); reused w3/wd/cx    */
#define OFF_ACT2  27672     /* 12800 : [64][8*25] (5x5 pad)                      */
#define OFF_ACT3  40472     /* 4096  : [p][512] NHWC flat                        */
#define OFF_RAW   44568     /* 1536  : [3][8*64]                                 */
#define OFF_W2S   46104     /* 4096  : w2 tap double buffer 2*2048               */
#define OFF_W1    50200     /* 864                                               */
#define OFF_V     51064     /* 512   : [p][64]                                   */
#define OFF_B     51576     /* 288   : b1 b2 b3 bd                               */
#define OFF_CW    51864     /* 128   : comp_w                                    */
#define OFF_VN2   51992     /* 8                                                 */
#define SMEM_FLOATS 52000
#define SMEM_BYTES  (SMEM_FLOATS * 4)

__device__ float    g_ysum[NB * 128];   /* zero-init; finalizer re-zeroes */
__device__ unsigned g_count;            /* zero-init; finalizer resets    */

/* ---- packed fp32x2 helpers (Blackwell FFMA2) ---- */
__device__ __forceinline__ u64 pack2(float lo, float hi) {
    u64 r; asm("mov.b64 %0, {%1, %2};" : "=l"(r) : "f"(lo), "f"(hi)); return r;
}
__device__ __forceinline__ void unpack2(u64 v, float& lo, float& hi) {
    asm("mov.b64 {%0, %1}, %2;" : "=f"(lo), "=f"(hi) : "l"(v));
}
__device__ __forceinline__ void fma2(u64& d, u64 a, u64 b) {
    asm("fma.rn.f32x2 %0, %1, %2, %0;" : "+l"(d) : "l"(a), "l"(b));
}

__device__ __forceinline__ void cp16(float* dst, const float* src) {
    unsigned s = (unsigned)__cvta_generic_to_shared(dst);
    asm volatile("cp.async.cg.shared.global [%0], [%1], 16;\n" :: "r"(s), "l"(src));
}
__device__ __forceinline__ void cp_commit() { asm volatile("cp.async.commit_group;\n"); }
__device__ __forceinline__ void cp_wait0()  { asm volatile("cp.async.wait_group 0;\n"); }

/* jax.image.resize 'linear' 8->16: sample i/2-0.25, edge-renormalized */
__device__ __forceinline__ void rtab(int i, int& a0, int& a1, float& w0, float& w1) {
    if (i == 0)       { a0 = 0; a1 = 0; w0 = 1.f;   w1 = 0.f;   }
    else if (i == 15) { a0 = 7; a1 = 7; w0 = 1.f;   w1 = 0.f;   }
    else if (i & 1)   { int m = i >> 1; a0 = m;     a1 = m + 1; w0 = 0.75f; w1 = 0.25f; }
    else              { int m = i >> 1; a0 = m - 1; a1 = m;     w0 = 0.25f; w1 = 0.75f; }
}

__global__ __launch_bounds__(T, 1)
void main_kernel(const float* __restrict__ images,
                 const float* __restrict__ w1, const float* __restrict__ b1,
                 const float* __restrict__ w2, const float* __restrict__ b2,
                 const float* __restrict__ w3, const float* __restrict__ b3,
                 const float* __restrict__ wd, const float* __restrict__ bd,
                 const float* __restrict__ c_x, const float* __restrict__ c_y,
                 const float* __restrict__ comp_w, const float* __restrict__ sigma,
                 float* __restrict__ out)
{
    extern __shared__ float sm[];
    const int tid = threadIdx.x;
    const int g0  = blockIdx.x * GP;

    float* s_b  = sm + OFF_B;
    float* s_cw = sm + OFF_CW;

    /* ---- init ---- */
    for (int i = tid; i < 864; i += T) sm[OFF_W1 + i] = w1[i];
    if (tid < 32)  s_b[tid]       = b1[tid];
    if (tid < 64)  s_b[32 + tid]  = b2[tid];
    if (tid < 128) s_b[96 + tid]  = b3[tid];
    if (tid < 64)  s_b[224 + tid] = bd[tid];
    if (tid < 128) s_cw[tid]      = comp_w[tid];
    for (int i = tid; i < OFF_ACT3 / 4; i += T)
        ((float4*)sm)[i] = make_float4(0.f, 0.f, 0.f, 0.f);

    for (int i = tid; i < 1536; i += T) {
        int c = i >> 9, rem = i & 511, p = rem >> 6, r = rem & 63;
        int iy = r >> 3, ix = r & 7;
        int g = g0 + p, b = g / NPP, pp = g % NPP;
        int py = pp / NPQ, px = pp % NPQ;
        sm[OFF_RAW + i] = images[((b * 96 + py * 2 + iy) * 96 + px * 2 + ix) * 3 + c];
    }
    __syncthreads();

    /* ---- resize 8x8 -> 16x16 into padded 17x17 planes ---- */
    for (int i = tid; i < 6144; i += T) {
        int c = i >> 11, rem = i & 2047, p = rem >> 8, r = rem & 255;
        int oy = r >> 4, ox = r & 15;
        int ay0, ay1, ax0, ax1; float wy0, wy1, wx0, wx1;
        rtab(oy, ay0, ay1, wy0, wy1);
        rtab(ox, ax0, ax1, wx0, wx1);
        const float* rp = sm + OFF_RAW + c * 512 + p * 64;
        float v00 = rp[ay0 * 8 + ax0], v01 = rp[ay0 * 8 + ax1];
        float v10 = rp[ay1 * 8 + ax0], v11 = rp[ay1 * 8 + ax1];
        sm[OFF_RS + c * 2312 + p * 289 + oy * 17 + ox] =
            wy0 * (wx0 * v00 + wx1 * v01) + wy1 * (wx0 * v10 + wx1 * v11);
    }
    __syncthreads();

    /* ---- conv1: M=512 N=32 K=27, TM=8, TN=8 (4 packed) ---- */
    {
        const int mt = tid >> 2, ng = tid & 3;
        const int p = mt >> 3, oy = mt & 7;
        u64 acc[8][4];
        #pragma unroll
        for (int i = 0; i < 8; i++)
            #pragma unroll
            for (int j = 0; j < 4; j++) acc[i][j] = 0ull;

        #pragma unroll 1
        for (int ky = 0; ky < 3; ky++)
        #pragma unroll 1
        for (int kx = 0; kx < 3; kx++) {
            #pragma unroll
            for (int c = 0; c < 3; c++) {
                const float* ap = sm + OFF_RS + c * 2312 + p * 289 + (2 * oy + ky) * 17 + kx;
                u64 aa[8];
                #pragma unroll
                for (int ox = 0; ox < 8; ox++) { float av = ap[2 * ox]; aa[ox] = pack2(av, av); }
                const u64* wp2 = (const u64*)(sm + OFF_W1 + ((ky * 3 + kx) * 3 + c) * 32 + ng * 8);
                u64 bb[4] = {wp2[0], wp2[1], wp2[2], wp2[3]};
                #pragma unroll
                for (int ox = 0; ox < 8; ox++)
                    #pragma unroll
                    for (int j = 0; j < 4; j++)
                        fma2(acc[ox][j], aa[ox], bb[j]);
            }
        }
        #pragma unroll
        for (int j = 0; j < 4; j++) {
            int oc0 = ng * 8 + 2 * j;
            float bi0 = s_b[oc0], bi1 = s_b[oc0 + 1];
            float* op0 = sm + OFF_ACT1 + oc0 * 648 + p * 81 + oy * 9;
            float* op1 = op0 + 648;
            #pragma unroll
            for (int ox = 0; ox < 8; ox++) {
                float lo, hi; unpack2(acc[ox][j], lo, hi);
                op0[ox] = fmaxf(lo + bi0, 0.f);
                op1[ox] = fmaxf(hi + bi1, 0.f);
            }
        }
    }
    __syncthreads();

    /* ---- conv2: M=128 N=64 K=288, TM=4, TN=8 (4 packed), per-tap cp.async ---- */
    {
        const int mt = tid >> 3, ng = tid & 7;
        const int p = mt >> 2, oy = mt & 3;
        u64 acc[4][4];
        #pragma unroll
        for (int i = 0; i < 4; i++)
            #pragma unroll
            for (int j = 0; j < 4; j++) acc[i][j] = 0ull;

        #pragma unroll
        for (int j = 0; j < 2; j++) {
            int i4 = tid + j * 256;
            cp16(sm + OFF_W2S + i4 * 4, w2 + i4 * 4);
        }
        cp_commit();

        #pragma unroll 1
        for (int t = 0; t < 9; t++) {
            cp_wait0();
            __syncthreads();
            if (t < 8) {
                #pragma unroll
                for (int j = 0; j < 2; j++) {
                    int i4 = tid + j * 256;
                    cp16(sm + OFF_W2S + ((t + 1) & 1) * 2048 + i4 * 4,
                         w2 + (t + 1) * 2048 + i4 * 4);
                }
                cp_commit();
            }
            const float* wb = sm + OFF_W2S + (t & 1) * 2048;
            int ky = t / 3, kx = t - ky * 3;
            const float* ap = sm + OFF_ACT1 + p * 81 + (2 * oy + ky) * 9 + kx;
            #pragma unroll 8
            for (int ic = 0; ic < 32; ic++) {
                u64 aa[4];
                #pragma unroll
                for (int ox = 0; ox < 4; ox++) { float av = ap[ic * 648 + 2 * ox]; aa[ox] = pack2(av, av); }
                const u64* wp2 = (const u64*)(wb + ic * 64 + ng * 8);
                u64 bb[4] = {wp2[0], wp2[1], wp2[2], wp2[3]};
                #pragma unroll
                for (int ox = 0; ox < 4; ox++)
                    #pragma unroll
                    for (int j = 0; j < 4; j++)
                        fma2(acc[ox][j], aa[ox], bb[j]);
            }
        }
        #pragma unroll
        for (int j = 0; j < 4; j++) {
            int oc0 = ng * 8 + 2 * j;
            float bi0 = s_b[32 + oc0], bi1 = s_b[32 + oc0 + 1];
            float* op0 = sm + OFF_ACT2 + oc0 * 200 + p * 25 + oy * 5;
            float* op1 = op0 + 200;
            #pragma unroll
            for (int ox = 0; ox < 4; ox++) {
                float lo, hi; unpack2(acc[ox][j], lo, hi);
                op0[ox] = fmaxf(lo + bi0, 0.f);
                op1[ox] = fmaxf(hi + bi1, 0.f);
            }
        }
    }
    __syncthreads();

    /* ---- conv3: M=32 N=128 K=576, TM=4(px), TN=4; taps fully unrolled,
           SAME-padding FMAs pruned at compile time; w3 double-buffered ---- */
    {
        const int p = tid >> 5, ng = tid & 31;
        u64 acc[4][2];
        #pragma unroll
        for (int i = 0; i < 4; i++) { acc[i][0] = 0ull; acc[i][1] = 0ull; }

        #pragma unroll
        for (int j = 0; j < 8; j++) {
            int i4 = tid + j * 256;
            cp16(sm + OFF_ACT1 + i4 * 4, w3 + i4 * 4);
        }
        cp_commit();

        #pragma unroll
        for (int t = 0; t < 9; t++) {
            cp_wait0();
            __syncthreads();
            if (t < 8) {
                #pragma unroll
                for (int j = 0; j < 8; j++) {
                    int i4 = tid + j * 256;
                    cp16(sm + OFF_ACT1 + ((t + 1) & 1) * 8192 + i4 * 4,
                         w3 + (t + 1) * 8192 + i4 * 4);
                }
                cp_commit();
            }
            const int ky = t / 3, kx = t % 3;      /* compile-time after unroll */
            const float* wb = sm + OFF_ACT1 + (t & 1) * 8192;
            const float* ap = sm + OFF_ACT2 + p * 25;
            #pragma unroll 4
            for (int ic = 0; ic < 64; ic++) {
                const u64* wp2 = (const u64*)(wb + ic * 128 + ng * 4);
                u64 bb0 = wp2[0], bb1 = wp2[1];
                #pragma unroll
                for (int px = 0; px < 4; px++) {
                    const int iy = 2 * (px >> 1) + ky, ix = 2 * (px & 1) + kx;
                    if (iy < 4 && ix < 4) {        /* pruned at compile time */
                        float a = ap[ic * 200 + iy * 5 + ix];
                        u64 aa = pack2(a, a);
                        fma2(acc[px][0], aa, bb0);
                        fma2(acc[px][1], aa, bb1);
                    }
                }
            }
        }
        #pragma unroll
        for (int j = 0; j < 2; j++) {
            int oc0 = ng * 4 + 2 * j;
            float bi0 = s_b[96 + oc0], bi1 = s_b[96 + oc0 + 1];
            #pragma unroll
            for (int px = 0; px < 4; px++) {
                float lo, hi; unpack2(acc[px][j], lo, hi);
                sm[OFF_ACT3 + p * 512 + px * 128 + oc0]     = fmaxf(lo + bi0, 0.f);
                sm[OFF_ACT3 + p * 512 + px * 128 + oc0 + 1] = fmaxf(hi + bi1, 0.f);
            }
        }
    }
    __syncthreads();

    /* ---- dense 512->64, 4 chunks of 128 rows, double-buffered in ACT1 ---- */
    {
        const int p = tid >> 5, lane = tid & 31, e0 = lane * 2;
        u64 accp = 0ull;

        #pragma unroll
        for (int j = 0; j < 8; j++) {
            int i4 = tid + j * 256;
            cp16(sm + OFF_ACT1 + i4 * 4, wd + i4 * 4);
        }
        cp_commit();

        #pragma unroll 1
        for (int c = 0; c < 4; c++) {
            cp_wait0();
            __syncthreads();
            if (c < 3) {
                #pragma unroll
                for (int j = 0; j < 8; j++) {
                    int i4 = tid + j * 256;
                    cp16(sm + OFF_ACT1 + ((c + 1) & 1) * 8192 + i4 * 4,
                         wd + (c + 1) * 8192 + i4 * 4);
                }
                cp_commit();
            }
            const float* xp = sm + OFF_ACT3 + p * 512 + c * 128;
            const float* wp = sm + OFF_ACT1 + (c & 1) * 8192;
            #pragma unroll 8
            for (int kk = 0; kk < 128; kk++) {
                float x = xp[kk];
                u64 xx = pack2(x, x);
                u64 ww = *(const u64*)(wp + kk * 64 + e0);
                fma2(accp, xx, ww);
            }
        }
        float lo, hi; unpack2(accp, lo, hi);
        sm[OFF_V + p * 64 + e0]     = lo + s_b[224 + e0];
        sm[OFF_V + p * 64 + e0 + 1] = hi + s_b[224 + e0 + 1];
    }
    __syncthreads();

    /* ---- head: vn2, stage c_x (stride-65 pad), d2 -> ow -> atomics ---- */
    if (tid < GP) {
        float a = 0.f;
        const float* vp = sm + OFF_V + tid * 64;
        #pragma unroll 8
        for (int e = 0; e < 64; e++) a = fmaf(vp[e], vp[e], a);
        sm[OFF_VN2 + tid] = a;
    }
    for (int i = tid; i < 8192; i += T) {
        int k = i >> 6, e = i & 63;
        sm[OFF_ACT1 + k * 65 + e] = c_x[i];
    }
    __syncthreads();

    {
        float inv_s2 = 1.f / (sigma[0] * sigma[0]);
        int k = tid & 127, pg = tid >> 7;
        u64 d01 = pack2(sm[OFF_VN2 + pg * 4],     sm[OFF_VN2 + pg * 4 + 1]);
        u64 d23 = pack2(sm[OFF_VN2 + pg * 4 + 2], sm[OFF_VN2 + pg * 4 + 3]);
        const u64 neg2 = pack2(-2.f, -2.f);
        const float* vp = sm + OFF_V + pg * 256;
        const float* ck = sm + OFF_ACT1 + k * 65;
        #pragma unroll 8
        for (int e = 0; e < 64; e++) {
            float cv = ck[e];
            u64 cc = pack2(cv, cv);
            u64 v01 = pack2(vp[e],       vp[64 + e]);
            u64 v23 = pack2(vp[128 + e], vp[192 + e]);
            u64 t01 = cc, t23 = cc;
            fma2(t01, neg2, v01);
            fma2(t23, neg2, v23);
            fma2(d01, cc, t01);
            fma2(d23, cc, t23);
        }
        float d[4];
        unpack2(d01, d[0], d[1]);
        unpack2(d23, d[2], d[3]);
        int b0 = (g0 + pg * 4)     / NPP;
        int b3 = (g0 + pg * 4 + 3) / NPP;
        float accA = 0.f, accB = 0.f;
        float cwk = s_cw[k];
        #pragma unroll
        for (int pp = 0; pp < 4; pp++) {
            float dd = fmaxf(d[pp], 0.f);
            float owv = fmaxf(cwk * expf(-dd * inv_s2), 1e-10f);
            int b = (g0 + pg * 4 + pp) / NPP;
            if (b == b0) accA += owv; else accB += owv;
        }
        atomicAdd(&g_ysum[b0 * 128 + k], accA);
        if (b3 != b0) atomicAdd(&g_ysum[b3 * 128 + k], accB);
    }

    /* ---- last-CTA finalize (replaces fin_kernel; aligns ncu onto main) ---- */
    __syncthreads();
    __shared__ unsigned s_rank;
    if (tid == 0) {
        __threadfence();
        s_rank = atomicAdd(&g_count, 1u);
    }
    __syncthreads();
    if (s_rank == NBLK - 1) {
        __threadfence();
        float* s_y   = sm + OFF_RS;          /* 2048 */
        float* yv2   = s_y + 2048;           /* 1280 */
        float* rsum  = yv2 + 1280;           /* 16   */
        for (int i = tid; i < NB * 128; i += T) {
            s_y[i] = g_ysum[i];
            g_ysum[i] = 0.f;                 /* reset for next replay */
        }
        if (tid == 0) g_count = 0u;
        __syncthreads();
        for (int k = tid; k < 128; k += T) {
            float n2 = 0.f;
            #pragma unroll
            for (int i = 0; i < 10; i++) { float c = c_y[k * 10 + i]; n2 = fmaf(c, c, n2); }
            float inv = 1.f / n2;
            #pragma unroll
            for (int i = 0; i < 10; i++) { float c = c_y[k * 10 + i]; yv2[k * 10 + i] = c * c * inv; }
        }
        if (tid < NB) {
            float s = 0.f;
            for (int k = 0; k < 128; k++) s += s_y[tid * 128 + k];
            rsum[tid] = s;
        }
        __syncthreads();
        if (tid < NB * 10) {
            int b = tid / 10, i = tid % 10;
            float a = 0.f;
            for (int k = 0; k < 128; k++) a = fmaf(s_y[b * 128 + k], yv2[k * 10 + i], a);
            out[tid] = a / rsum[b];
        }
    }
}

extern "C" void kernel_launch(void* const* d_in, const int* in_sizes, int n_in,
                              void* d_out, int out_size) {
    (void)in_sizes; (void)n_in; (void)out_size;
    const float* images = (const float*)d_in[0];
    const float* w1     = (const float*)d_in[1];
    const float* b1     = (const float*)d_in[2];
    const float* w2     = (const float*)d_in[3];
    const float* b2     = (const float*)d_in[4];
    const float* w3     = (const float*)d_in[5];
    const float* b3     = (const float*)d_in[6];
    const float* wd     = (const float*)d_in[7];
    const float* bd     = (const float*)d_in[8];
    const float* c_x    = (const float*)d_in[9];
    const float* c_y    = (const float*)d_in[10];
    const float* comp_w = (const float*)d_in[11];
    const float* sigma  = (const float*)d_in[12];
    float* out = (float*)d_out;

    cudaFuncSetAttribute(main_kernel, cudaFuncAttributeMaxDynamicSharedMemorySize, SMEM_BYTES);

    main_kernel<<<NBLK, T, SMEM_BYTES>>>(images, w1, b1, w2, b2, w3, b3,
                                         wd, bd, c_x, c_y, comp_w, sigma, out);
}

// round 7
// speedup vs baseline: 1.4735x; 1.1022x over previous
#include <cuda_runtime.h>
#include <math.h>

typedef unsigned long long u64;

#define T 256
#define GP 8
#define NB   16
#define NPQ  45
#define NPP  (NPQ*NPQ)
#define NTOT (NB*NPP)
#define NBLK (NTOT/GP)      /* 4050 CTAs */

/* float offsets in dynamic smem */
#define OFF_RS    0         /* 6936  : resized planar [3][8p][289] (17x17)       */
#define OFF_ACT1  6936      /* 24192 : [32ic][9iy][84] (p*9+ix); reused w3/wd/cx */
#define OFF_ACT2  31128     /* 12800 : [64ic][8p][25] (5x5 pad)                  */
#define OFF_ACT3  43928     /* 4128  : [8p][516] (px*129+oc)                     */
#define OFF_RAW   48056     /* 1536  : [3][8p][64]                               */
#define OFF_W2S   49592     /* 4096  : w2 tap double buffer                      */
#define OFF_W1    53688     /* 864                                               */
#define OFF_V     54552     /* 512   : [p][64]                                   */
#define OFF_B     55064     /* 288   : b1 b2 b3 bd                               */
#define OFF_CW    55352     /* 128                                               */
#define OFF_VN2   55480     /* 8                                                 */
#define SMEM_FLOATS 55488
#define SMEM_BYTES  (SMEM_FLOATS * 4)

__device__ float    g_ysum[NB * 128];
__device__ unsigned g_count;

/* ---- packed fp32x2 ---- */
__device__ __forceinline__ u64 pack2(float lo, float hi) {
    u64 r; asm("mov.b64 %0, {%1, %2};" : "=l"(r) : "f"(lo), "f"(hi)); return r;
}
__device__ __forceinline__ void unpack2(u64 v, float& lo, float& hi) {
    asm("mov.b64 {%0, %1}, %2;" : "=f"(lo), "=f"(hi) : "l"(v));
}
__device__ __forceinline__ void fma2(u64& d, u64 a, u64 b) {
    asm("fma.rn.f32x2 %0, %1, %2, %0;" : "+l"(d) : "l"(a), "l"(b));
}

__device__ __forceinline__ void cp16(float* dst, const float* src) {
    unsigned s = (unsigned)__cvta_generic_to_shared(dst);
    asm volatile("cp.async.cg.shared.global [%0], [%1], 16;\n" :: "r"(s), "l"(src));
}
__device__ __forceinline__ void cp_commit() { asm volatile("cp.async.commit_group;\n"); }
__device__ __forceinline__ void cp_wait0()  { asm volatile("cp.async.wait_group 0;\n"); }

/* jax.image.resize 'linear' 8->16 */
__device__ __forceinline__ void rtab(int i, int& a0, int& a1, float& w0, float& w1) {
    if (i == 0)       { a0 = 0; a1 = 0; w0 = 1.f;   w1 = 0.f;   }
    else if (i == 15) { a0 = 7; a1 = 7; w0 = 1.f;   w1 = 0.f;   }
    else if (i & 1)   { int m = i >> 1; a0 = m;     a1 = m + 1; w0 = 0.75f; w1 = 0.25f; }
    else              { int m = i >> 1; a0 = m - 1; a1 = m;     w0 = 0.25f; w1 = 0.75f; }
}

__global__ __launch_bounds__(T, 1)
void main_kernel(const float* __restrict__ images,
                 const float* __restrict__ w1, const float* __restrict__ b1,
                 const float* __restrict__ w2, const float* __restrict__ b2,
                 const float* __restrict__ w3, const float* __restrict__ b3,
                 const float* __restrict__ wd, const float* __restrict__ bd,
                 const float* __restrict__ c_x, const float* __restrict__ c_y,
                 const float* __restrict__ comp_w, const float* __restrict__ sigma,
                 float* __restrict__ out)
{
    extern __shared__ float sm[];
    const int tid  = threadIdx.x;
    const int g0   = blockIdx.x * GP;
    const int wid  = tid >> 5;
    const int lane = tid & 31;

    float* s_b  = sm + OFF_B;
    float* s_cw = sm + OFF_CW;

    /* ---- init ---- */
    for (int i = tid; i < 864; i += T) sm[OFF_W1 + i] = w1[i];
    if (tid < 32)  s_b[tid]       = b1[tid];
    if (tid < 64)  s_b[32 + tid]  = b2[tid];
    if (tid < 128) s_b[96 + tid]  = b3[tid];
    if (tid < 64)  s_b[224 + tid] = bd[tid];
    if (tid < 128) s_cw[tid]      = comp_w[tid];
    for (int i = tid; i < OFF_RAW / 4; i += T)          /* zero rs+act1+act2+act3 */
        ((float4*)sm)[i] = make_float4(0.f, 0.f, 0.f, 0.f);

    for (int i = tid; i < 1536; i += T) {
        int c = i >> 9, rem = i & 511, p = rem >> 6, r = rem & 63;
        int iy = r >> 3, ix = r & 7;
        int g = g0 + p, b = g / NPP, pp = g % NPP;
        int py = pp / NPQ, px = pp % NPQ;
        sm[OFF_RAW + i] = images[((b * 96 + py * 2 + iy) * 96 + px * 2 + ix) * 3 + c];
    }
    __syncthreads();

    /* ---- resize 8x8 -> 16x16 into padded 17x17 planes ---- */
    for (int i = tid; i < 6144; i += T) {
        int c = i >> 11, rem = i & 2047, p = rem >> 8, r = rem & 255;
        int oy = r >> 4, ox = r & 15;
        int ay0, ay1, ax0, ax1; float wy0, wy1, wx0, wx1;
        rtab(oy, ay0, ay1, wy0, wy1);
        rtab(ox, ax0, ax1, wx0, wx1);
        const float* rp = sm + OFF_RAW + c * 512 + p * 64;
        float v00 = rp[ay0 * 8 + ax0], v01 = rp[ay0 * 8 + ax1];
        float v10 = rp[ay1 * 8 + ax0], v11 = rp[ay1 * 8 + ax1];
        sm[OFF_RS + c * 2312 + p * 289 + oy * 17 + ox] =
            wy0 * (wx0 * v00 + wx1 * v01) + wy1 * (wx0 * v10 + wx1 * v11);
    }
    __syncthreads();

    /* ---- conv1: M=512 N=32 K=27, TM=8, TN=8; writes act1 [ic][iy*84 + p*9+ix] ---- */
    {
        const int mt = tid >> 2, ng = tid & 3;
        const int p = mt >> 3, oy = mt & 7;
        u64 acc[8][4];
        #pragma unroll
        for (int i = 0; i < 8; i++)
            #pragma unroll
            for (int j = 0; j < 4; j++) acc[i][j] = 0ull;

        #pragma unroll 1
        for (int ky = 0; ky < 3; ky++)
        #pragma unroll 1
        for (int kx = 0; kx < 3; kx++) {
            #pragma unroll
            for (int c = 0; c < 3; c++) {
                const float* ap = sm + OFF_RS + c * 2312 + p * 289 + (2 * oy + ky) * 17 + kx;
                u64 aa[8];
                #pragma unroll
                for (int ox = 0; ox < 8; ox++) { float av = ap[2 * ox]; aa[ox] = pack2(av, av); }
                const u64* wp2 = (const u64*)(sm + OFF_W1 + ((ky * 3 + kx) * 3 + c) * 32 + ng * 8);
                u64 bb[4] = {wp2[0], wp2[1], wp2[2], wp2[3]};
                #pragma unroll
                for (int ox = 0; ox < 8; ox++)
                    #pragma unroll
                    for (int j = 0; j < 4; j++)
                        fma2(acc[ox][j], aa[ox], bb[j]);
            }
        }
        #pragma unroll
        for (int j = 0; j < 4; j++) {
            int oc0 = ng * 8 + 2 * j;
            float bi0 = s_b[oc0], bi1 = s_b[oc0 + 1];
            float* op0 = sm + OFF_ACT1 + oc0 * 756 + oy * 84 + p * 9;
            float* op1 = op0 + 756;
            #pragma unroll
            for (int ox = 0; ox < 8; ox++) {
                float lo, hi; unpack2(acc[ox][j], lo, hi);
                op0[ox] = fmaxf(lo + bi0, 0.f);
                op1[ox] = fmaxf(hi + bi1, 0.f);
            }
        }
    }
    __syncthreads();

    /* ---- conv2: warp=oc-group(8), lanes=(p0,pix); weights BROADCAST ---- */
    {
        const int oc0 = wid * 8;
        const int p0 = lane >> 4, pix = lane & 15, oy = pix >> 2, ox = pix & 3;
        u64 acc[4][4];
        #pragma unroll
        for (int i = 0; i < 4; i++)
            #pragma unroll
            for (int j = 0; j < 4; j++) acc[i][j] = 0ull;

        #pragma unroll
        for (int j = 0; j < 2; j++) {
            int i4 = tid + j * 256;
            cp16(sm + OFF_W2S + i4 * 4, w2 + i4 * 4);
        }
        cp_commit();

        #pragma unroll 1
        for (int t = 0; t < 9; t++) {
            cp_wait0();
            __syncthreads();
            if (t < 8) {
                #pragma unroll
                for (int j = 0; j < 2; j++) {
                    int i4 = tid + j * 256;
                    cp16(sm + OFF_W2S + ((t + 1) & 1) * 2048 + i4 * 4,
                         w2 + (t + 1) * 2048 + i4 * 4);
                }
                cp_commit();
            }
            int ky = t / 3, kx = t - ky * 3;
            const float* ab = sm + OFF_ACT1 + (2 * oy + ky) * 84 + p0 * 9 + (2 * ox + kx);
            const float* wb = sm + OFF_W2S + (t & 1) * 2048 + oc0;
            #pragma unroll 8
            for (int ic = 0; ic < 32; ic++) {
                ulonglong2 w01 = *(const ulonglong2*)(wb + ic * 64);       /* broadcast */
                ulonglong2 w23 = *(const ulonglong2*)(wb + ic * 64 + 4);
                const float* ai = ab + ic * 756;
                #pragma unroll
                for (int i = 0; i < 4; i++) {
                    float av = ai[18 * i];
                    u64 aa = pack2(av, av);
                    fma2(acc[i][0], aa, w01.x);
                    fma2(acc[i][1], aa, w01.y);
                    fma2(acc[i][2], aa, w23.x);
                    fma2(acc[i][3], aa, w23.y);
                }
            }
        }
        #pragma unroll
        for (int j = 0; j < 4; j++) {
            int oc = oc0 + 2 * j;
            float bi0 = s_b[32 + oc], bi1 = s_b[32 + oc + 1];
            #pragma unroll
            for (int i = 0; i < 4; i++) {
                int p = p0 + 2 * i;
                float lo, hi; unpack2(acc[i][j], lo, hi);
                float* o = sm + OFF_ACT2 + oc * 200 + p * 25 + oy * 5 + ox;
                o[0]   = fmaxf(lo + bi0, 0.f);
                o[200] = fmaxf(hi + bi1, 0.f);
            }
        }
    }
    __syncthreads();

    /* ---- conv3: warp=oc-group(16), lanes=(p,px); weights BROADCAST ---- */
    {
        const int oc0 = wid * 16;
        const int p = lane >> 2, px = lane & 3;
        const int oy2 = px >> 1, ox2 = px & 1;
        u64 acc[8];
        #pragma unroll
        for (int j = 0; j < 8; j++) acc[j] = 0ull;

        #pragma unroll
        for (int j = 0; j < 8; j++) {
            int i4 = tid + j * 256;
            cp16(sm + OFF_ACT1 + i4 * 4, w3 + i4 * 4);
        }
        cp_commit();

        #pragma unroll 1
        for (int t = 0; t < 9; t++) {
            cp_wait0();
            __syncthreads();
            if (t < 8) {
                #pragma unroll
                for (int j = 0; j < 8; j++) {
                    int i4 = tid + j * 256;
                    cp16(sm + OFF_ACT1 + ((t + 1) & 1) * 8192 + i4 * 4,
                         w3 + (t + 1) * 8192 + i4 * 4);
                }
                cp_commit();
            }
            int ky = t / 3, kx = t - ky * 3;
            /* padded 5x5 act2: iy,ix up to 4 read zeros */
            const float* ap = sm + OFF_ACT2 + p * 25 + (2 * oy2 + ky) * 5 + (2 * ox2 + kx);
            const float* wb = sm + OFF_ACT1 + (t & 1) * 8192 + oc0;
            #pragma unroll 4
            for (int ic = 0; ic < 64; ic++) {
                float av = ap[ic * 200];
                u64 aa = pack2(av, av);
                ulonglong2 w01 = *(const ulonglong2*)(wb + ic * 128);      /* broadcast */
                ulonglong2 w23 = *(const ulonglong2*)(wb + ic * 128 + 4);
                ulonglong2 w45 = *(const ulonglong2*)(wb + ic * 128 + 8);
                ulonglong2 w67 = *(const ulonglong2*)(wb + ic * 128 + 12);
                fma2(acc[0], aa, w01.x); fma2(acc[1], aa, w01.y);
                fma2(acc[2], aa, w23.x); fma2(acc[3], aa, w23.y);
                fma2(acc[4], aa, w45.x); fma2(acc[5], aa, w45.y);
                fma2(acc[6], aa, w67.x); fma2(acc[7], aa, w67.y);
            }
        }
        #pragma unroll
        for (int j = 0; j < 8; j++) {
            int oc = oc0 + 2 * j;
            float lo, hi; unpack2(acc[j], lo, hi);
            float* o = sm + OFF_ACT3 + p * 516 + px * 129 + oc;
            o[0] = fmaxf(lo + s_b[96 + oc], 0.f);
            o[1] = fmaxf(hi + s_b[96 + oc + 1], 0.f);
        }
    }
    __syncthreads();

    /* ---- dense 512->64: warp=oc-group(8), lanes=(kq,p); butterfly K-reduce ---- */
    {
        const int oc0 = wid * 8;
        const int kq = lane >> 3, pl = lane & 7;
        u64 acc[4] = {0ull, 0ull, 0ull, 0ull};

        #pragma unroll 1
        for (int s = 0; s < 2; s++) {
            __syncthreads();
            /* stage wd rows f = kq*128 + s*64 + rr into [kq*4104 + rr*64 + col] */
            #pragma unroll
            for (int j = 0; j < 16; j++) {
                int idx = tid + j * 256;            /* 0..4095 cp16 units */
                int row = idx >> 4;                 /* 0..255 */
                int col = (idx & 15) * 4;
                int kqs = row >> 6, rr = row & 63;
                cp16(sm + OFF_ACT1 + kqs * 4104 + rr * 64 + col,
                     wd + (kqs * 128 + s * 64 + rr) * 64 + col);
            }
            cp_commit();
            cp_wait0();
            __syncthreads();

            const float* xp = sm + OFF_ACT3 + pl * 516 + kq * 129 + s * 64;
            const float* wp = sm + OFF_ACT1 + kq * 4104 + oc0;
            #pragma unroll 8
            for (int kk = 0; kk < 64; kk++) {
                float x = xp[kk];
                u64 xx = pack2(x, x);
                ulonglong2 w01 = *(const ulonglong2*)(wp + kk * 64);
                ulonglong2 w23 = *(const ulonglong2*)(wp + kk * 64 + 4);
                fma2(acc[0], xx, w01.x); fma2(acc[1], xx, w01.y);
                fma2(acc[2], xx, w23.x); fma2(acc[3], xx, w23.y);
            }
        }
        /* butterfly reduce over kq (lane bits 3,4) */
        float r[8];
        #pragma unroll
        for (int j = 0; j < 4; j++) unpack2(acc[j], r[2 * j], r[2 * j + 1]);
        #pragma unroll
        for (int j = 0; j < 8; j++) {
            r[j] += __shfl_xor_sync(0xffffffffu, r[j], 8);
            r[j] += __shfl_xor_sync(0xffffffffu, r[j], 16);
        }
        if (kq == 0) {
            #pragma unroll
            for (int j = 0; j < 8; j++) {
                int e = oc0 + j;
                sm[OFF_V + pl * 64 + e] = r[j] + s_b[224 + e];
            }
        }
    }
    __syncthreads();

    /* ---- head: vn2, stage c_x (stride 65), d2 -> ow -> atomics ---- */
    if (tid < GP) {
        float a = 0.f;
        const float* vp = sm + OFF_V + tid * 64;
        #pragma unroll 8
        for (int e = 0; e < 64; e++) a = fmaf(vp[e], vp[e], a);
        sm[OFF_VN2 + tid] = a;
    }
    for (int i = tid; i < 8192; i += T) {
        int k = i >> 6, e = i & 63;
        sm[OFF_ACT1 + k * 65 + e] = c_x[i];
    }
    __syncthreads();

    {
        float inv_s2 = 1.f / (sigma[0] * sigma[0]);
        int k = tid & 127, pg = tid >> 7;
        u64 d01 = pack2(sm[OFF_VN2 + pg * 4],     sm[OFF_VN2 + pg * 4 + 1]);
        u64 d23 = pack2(sm[OFF_VN2 + pg * 4 + 2], sm[OFF_VN2 + pg * 4 + 3]);
        const u64 neg2 = pack2(-2.f, -2.f);
        const float* vp = sm + OFF_V + pg * 256;
        const float* ck = sm + OFF_ACT1 + k * 65;
        #pragma unroll 8
        for (int e = 0; e < 64; e++) {
            float cv = ck[e];
            u64 cc = pack2(cv, cv);
            u64 v01 = pack2(vp[e],       vp[64 + e]);
            u64 v23 = pack2(vp[128 + e], vp[192 + e]);
            u64 t01 = cc, t23 = cc;
            fma2(t01, neg2, v01);
            fma2(t23, neg2, v23);
            fma2(d01, cc, t01);
            fma2(d23, cc, t23);
        }
        float d[4];
        unpack2(d01, d[0], d[1]);
        unpack2(d23, d[2], d[3]);
        int b0 = (g0 + pg * 4)     / NPP;
        int b3 = (g0 + pg * 4 + 3) / NPP;
        float accA = 0.f, accB = 0.f;
        float cwk = s_cw[k];
        #pragma unroll
        for (int pp = 0; pp < 4; pp++) {
            float dd = fmaxf(d[pp], 0.f);
            float owv = fmaxf(cwk * expf(-dd * inv_s2), 1e-10f);
            int b = (g0 + pg * 4 + pp) / NPP;
            if (b == b0) accA += owv; else accB += owv;
        }
        atomicAdd(&g_ysum[b0 * 128 + k], accA);
        if (b3 != b0) atomicAdd(&g_ysum[b3 * 128 + k], accB);
    }

    /* ---- last-CTA finalize ---- */
    __syncthreads();
    __shared__ unsigned s_rank;
    if (tid == 0) {
        __threadfence();
        s_rank = atomicAdd(&g_count, 1u);
    }
    __syncthreads();
    if (s_rank == NBLK - 1) {
        __threadfence();
        float* s_y   = sm + OFF_RS;
        float* yv2   = s_y + 2048;
        float* rsum  = yv2 + 1280;
        for (int i = tid; i < NB * 128; i += T) {
            s_y[i] = g_ysum[i];
            g_ysum[i] = 0.f;
        }
        if (tid == 0) g_count = 0u;
        __syncthreads();
        for (int k = tid; k < 128; k += T) {
            float n2 = 0.f;
            #pragma unroll
            for (int i = 0; i < 10; i++) { float c = c_y[k * 10 + i]; n2 = fmaf(c, c, n2); }
            float inv = 1.f / n2;
            #pragma unroll
            for (int i = 0; i < 10; i++) { float c = c_y[k * 10 + i]; yv2[k * 10 + i] = c * c * inv; }
        }
        if (tid < NB) {
            float s = 0.f;
            for (int k = 0; k < 128; k++) s += s_y[tid * 128 + k];
            rsum[tid] = s;
        }
        __syncthreads();
        if (tid < NB * 10) {
            int b = tid / 10, i = tid % 10;
            float a = 0.f;
            for (int k = 0; k < 128; k++) a = fmaf(s_y[b * 128 + k], yv2[k * 10 + i], a);
            out[tid] = a / rsum[b];
        }
    }
}

extern "C" void kernel_launch(void* const* d_in, const int* in_sizes, int n_in,
                              void* d_out, int out_size) {
    (void)in_sizes; (void)n_in; (void)out_size;
    const float* images = (const float*)d_in[0];
    const float* w1     = (const float*)d_in[1];
    const float* b1     = (const float*)d_in[2];
    const float* w2     = (const float*)d_in[3];
    const float* b2     = (const float*)d_in[4];
    const float* w3     = (const float*)d_in[5];
    const float* b3     = (const float*)d_in[6];
    const float* wd     = (const float*)d_in[7];
    const float* bd     = (const float*)d_in[8];
    const float* c_x    = (const float*)d_in[9];
    const float* c_y    = (const float*)d_in[10];
    const float* comp_w = (const float*)d_in[11];
    const float* sigma  = (const float*)d_in[12];
    float* out = (float*)d_out;

    cudaFuncSetAttribute(main_kernel, cudaFuncAttributeMaxDynamicSharedMemorySize, SMEM_BYTES);

    main_kernel<<<NBLK, T, SMEM_BYTES>>>(images, w1, b1, w2, b2, w3, b3,
                                         wd, bd, c_x, c_y, comp_w, sigma, out);
}

// round 8
// speedup vs baseline: 1.7093x; 1.1600x over previous
#include <cuda_runtime.h>
#include <math.h>

typedef unsigned long long u64;

#define T 256
#define GP 8
#define NB   16
#define NPQ  45
#define NPP  (NPQ*NPQ)
#define NTOT (NB*NPP)
#define NBLK (NTOT/GP)      /* 4050 CTAs */

/* float offsets in dynamic smem */
#define OFF_RS    0         /* 6936  : resized planar [3][8p][289] (17x17)       */
#define OFF_ACT1  6936      /* 24192 : [32ic][9iy][84] (p*9+ix); reused w3/wd/cx */
#define OFF_ACT2  31128     /* 14336 : [64ic][8p][28] (5x5 in 28-stride, pad 0)  */
#define OFF_ACT3  45464     /* 4128  : [8p][516] (px*129+oc)                     */
#define OFF_RAW   49592     /* 1536  : [3][8p][64]                               */
#define OFF_W2S   51128     /* 4096  : w2 tap double buffer                      */
#define OFF_W1    55224     /* 864                                               */
#define OFF_V     56088     /* 512   : [p][64]                                   */
#define OFF_B     56600     /* 288   : b1 b2 b3 bd                               */
#define OFF_CW    56888     /* 128                                               */
#define OFF_VN2   57016     /* 8                                                 */
#define SMEM_FLOATS 57024
#define SMEM_BYTES  (SMEM_FLOATS * 4)

__device__ float    g_ysum[NB * 128];
__device__ unsigned g_count;

/* ---- packed fp32x2 ---- */
__device__ __forceinline__ u64 pack2(float lo, float hi) {
    u64 r; asm("mov.b64 %0, {%1, %2};" : "=l"(r) : "f"(lo), "f"(hi)); return r;
}
__device__ __forceinline__ void unpack2(u64 v, float& lo, float& hi) {
    asm("mov.b64 {%0, %1}, %2;" : "=f"(lo), "=f"(hi) : "l"(v));
}
__device__ __forceinline__ void fma2(u64& d, u64 a, u64 b) {
    asm("fma.rn.f32x2 %0, %1, %2, %0;" : "+l"(d) : "l"(a), "l"(b));
}

__device__ __forceinline__ void cp16(float* dst, const float* src) {
    unsigned s = (unsigned)__cvta_generic_to_shared(dst);
    asm volatile("cp.async.cg.shared.global [%0], [%1], 16;\n" :: "r"(s), "l"(src));
}
__device__ __forceinline__ void cp_commit() { asm volatile("cp.async.commit_group;\n"); }
__device__ __forceinline__ void cp_wait0()  { asm volatile("cp.async.wait_group 0;\n"); }

/* jax.image.resize 'linear' 8->16 */
__device__ __forceinline__ void rtab(int i, int& a0, int& a1, float& w0, float& w1) {
    if (i == 0)       { a0 = 0; a1 = 0; w0 = 1.f;   w1 = 0.f;   }
    else if (i == 15) { a0 = 7; a1 = 7; w0 = 1.f;   w1 = 0.f;   }
    else if (i & 1)   { int m = i >> 1; a0 = m;     a1 = m + 1; w0 = 0.75f; w1 = 0.25f; }
    else              { int m = i >> 1; a0 = m - 1; a1 = m;     w0 = 0.25f; w1 = 0.75f; }
}

__global__ __launch_bounds__(T, 1)
void main_kernel(const float* __restrict__ images,
                 const float* __restrict__ w1, const float* __restrict__ b1,
                 const float* __restrict__ w2, const float* __restrict__ b2,
                 const float* __restrict__ w3, const float* __restrict__ b3,
                 const float* __restrict__ wd, const float* __restrict__ bd,
                 const float* __restrict__ c_x, const float* __restrict__ c_y,
                 const float* __restrict__ comp_w, const float* __restrict__ sigma,
                 float* __restrict__ out)
{
    extern __shared__ float sm[];
    const int tid  = threadIdx.x;
    const int g0   = blockIdx.x * GP;
    const int wid  = tid >> 5;
    const int lane = tid & 31;

    float* s_b  = sm + OFF_B;
    float* s_cw = sm + OFF_CW;

    /* ---- init ---- */
    for (int i = tid; i < 864; i += T) sm[OFF_W1 + i] = w1[i];
    if (tid < 32)  s_b[tid]       = b1[tid];
    if (tid < 64)  s_b[32 + tid]  = b2[tid];
    if (tid < 128) s_b[96 + tid]  = b3[tid];
    if (tid < 64)  s_b[224 + tid] = bd[tid];
    if (tid < 128) s_cw[tid]      = comp_w[tid];
    for (int i = tid; i < OFF_RAW / 4; i += T)          /* zero rs+act1+act2+act3 */
        ((float4*)sm)[i] = make_float4(0.f, 0.f, 0.f, 0.f);

    for (int i = tid; i < 1536; i += T) {
        int c = i >> 9, rem = i & 511, p = rem >> 6, r = rem & 63;
        int iy = r >> 3, ix = r & 7;
        int g = g0 + p, b = g / NPP, pp = g % NPP;
        int py = pp / NPQ, px = pp % NPQ;
        sm[OFF_RAW + i] = images[((b * 96 + py * 2 + iy) * 96 + px * 2 + ix) * 3 + c];
    }
    __syncthreads();

    /* ---- resize 8x8 -> 16x16 into padded 17x17 planes ---- */
    for (int i = tid; i < 6144; i += T) {
        int c = i >> 11, rem = i & 2047, p = rem >> 8, r = rem & 255;
        int oy = r >> 4, ox = r & 15;
        int ay0, ay1, ax0, ax1; float wy0, wy1, wx0, wx1;
        rtab(oy, ay0, ay1, wy0, wy1);
        rtab(ox, ax0, ax1, wx0, wx1);
        const float* rp = sm + OFF_RAW + c * 512 + p * 64;
        float v00 = rp[ay0 * 8 + ax0], v01 = rp[ay0 * 8 + ax1];
        float v10 = rp[ay1 * 8 + ax0], v11 = rp[ay1 * 8 + ax1];
        sm[OFF_RS + c * 2312 + p * 289 + oy * 17 + ox] =
            wy0 * (wx0 * v00 + wx1 * v01) + wy1 * (wx0 * v10 + wx1 * v11);
    }
    __syncthreads();

    /* ---- conv1: M=512 N=32 K=27, TM=8, TN=8; writes act1 [ic][iy*84 + p*9+ix] ---- */
    {
        const int mt = tid >> 2, ng = tid & 3;
        const int p = mt >> 3, oy = mt & 7;
        u64 acc[8][4];
        #pragma unroll
        for (int i = 0; i < 8; i++)
            #pragma unroll
            for (int j = 0; j < 4; j++) acc[i][j] = 0ull;

        #pragma unroll 1
        for (int ky = 0; ky < 3; ky++)
        #pragma unroll 1
        for (int kx = 0; kx < 3; kx++) {
            #pragma unroll
            for (int c = 0; c < 3; c++) {
                const float* ap = sm + OFF_RS + c * 2312 + p * 289 + (2 * oy + ky) * 17 + kx;
                u64 aa[8];
                #pragma unroll
                for (int ox = 0; ox < 8; ox++) { float av = ap[2 * ox]; aa[ox] = pack2(av, av); }
                const u64* wp2 = (const u64*)(sm + OFF_W1 + ((ky * 3 + kx) * 3 + c) * 32 + ng * 8);
                u64 bb[4] = {wp2[0], wp2[1], wp2[2], wp2[3]};
                #pragma unroll
                for (int ox = 0; ox < 8; ox++)
                    #pragma unroll
                    for (int j = 0; j < 4; j++)
                        fma2(acc[ox][j], aa[ox], bb[j]);
            }
        }
        #pragma unroll
        for (int j = 0; j < 4; j++) {
            int oc0 = ng * 8 + 2 * j;
            float bi0 = s_b[oc0], bi1 = s_b[oc0 + 1];
            float* op0 = sm + OFF_ACT1 + oc0 * 756 + oy * 84 + p * 9;
            float* op1 = op0 + 756;
            #pragma unroll
            for (int ox = 0; ox < 8; ox++) {
                float lo, hi; unpack2(acc[ox][j], lo, hi);
                op0[ox] = fmaxf(lo + bi0, 0.f);
                op1[ox] = fmaxf(hi + bi1, 0.f);
            }
        }
    }
    __syncthreads();

    /* ---- conv2: warp=oc-group(8), lanes=(p0,pix); weights BROADCAST ---- */
    {
        const int oc0 = wid * 8;
        const int p0 = lane >> 4, pix = lane & 15, oy = pix >> 2, ox = pix & 3;
        u64 acc[4][4];
        #pragma unroll
        for (int i = 0; i < 4; i++)
            #pragma unroll
            for (int j = 0; j < 4; j++) acc[i][j] = 0ull;

        #pragma unroll
        for (int j = 0; j < 2; j++) {
            int i4 = tid + j * 256;
            cp16(sm + OFF_W2S + i4 * 4, w2 + i4 * 4);
        }
        cp_commit();

        #pragma unroll 1
        for (int t = 0; t < 9; t++) {
            cp_wait0();
            __syncthreads();
            if (t < 8) {
                #pragma unroll
                for (int j = 0; j < 2; j++) {
                    int i4 = tid + j * 256;
                    cp16(sm + OFF_W2S + ((t + 1) & 1) * 2048 + i4 * 4,
                         w2 + (t + 1) * 2048 + i4 * 4);
                }
                cp_commit();
            }
            int ky = t / 3, kx = t - ky * 3;
            const float* ab = sm + OFF_ACT1 + (2 * oy + ky) * 84 + p0 * 9 + (2 * ox + kx);
            const float* wb = sm + OFF_W2S + (t & 1) * 2048 + oc0;
            #pragma unroll 8
            for (int ic = 0; ic < 32; ic++) {
                ulonglong2 w01 = *(const ulonglong2*)(wb + ic * 64);
                ulonglong2 w23 = *(const ulonglong2*)(wb + ic * 64 + 4);
                const float* ai = ab + ic * 756;
                #pragma unroll
                for (int i = 0; i < 4; i++) {
                    float av = ai[18 * i];
                    u64 aa = pack2(av, av);
                    fma2(acc[i][0], aa, w01.x);
                    fma2(acc[i][1], aa, w01.y);
                    fma2(acc[i][2], aa, w23.x);
                    fma2(acc[i][3], aa, w23.y);
                }
            }
        }
        #pragma unroll
        for (int j = 0; j < 4; j++) {
            int oc = oc0 + 2 * j;
            float bi0 = s_b[32 + oc], bi1 = s_b[32 + oc + 1];
            #pragma unroll
            for (int i = 0; i < 4; i++) {
                int p = p0 + 2 * i;
                float lo, hi; unpack2(acc[i][j], lo, hi);
                float* o = sm + OFF_ACT2 + oc * 224 + p * 28 + oy * 5 + ox;
                o[0]   = fmaxf(lo + bi0, 0.f);
                o[224] = fmaxf(hi + bi1, 0.f);
            }
        }
    }
    __syncthreads();

    /* ---- conv3: warp = 16 oc; lane = (m-pair, oc-octet) so weight LDS carries
           2 distinct addresses/instr (full-width wavefronts, not broadcast) ---- */
    {
        const int oc0 = wid * 16;
        const int ocg = lane & 1;            /* 8-oc group within warp  */
        const int mgp = lane >> 1;           /* 0..15 : (p, px-half)    */
        const int p   = mgp >> 1;
        const int pxh = mgp & 1;             /* oy2 of the px pair      */
        u64 acc[2][4];
        #pragma unroll
        for (int i = 0; i < 2; i++)
            #pragma unroll
            for (int j = 0; j < 4; j++) acc[i][j] = 0ull;

        #pragma unroll
        for (int j = 0; j < 8; j++) {
            int i4 = tid + j * 256;
            cp16(sm + OFF_ACT1 + i4 * 4, w3 + i4 * 4);
        }
        cp_commit();

        #pragma unroll 1
        for (int t = 0; t < 9; t++) {
            cp_wait0();
            __syncthreads();
            if (t < 8) {
                #pragma unroll
                for (int j = 0; j < 8; j++) {
                    int i4 = tid + j * 256;
                    cp16(sm + OFF_ACT1 + ((t + 1) & 1) * 8192 + i4 * 4,
                         w3 + (t + 1) * 8192 + i4 * 4);
                }
                cp_commit();
            }
            int ky = t / 3, kx = t - (t / 3) * 3;
            const int iy = 2 * pxh + ky;
            if (iy < 4) {                     /* uniform per lane over whole tap */
                const float* wb = sm + OFF_ACT1 + (t & 1) * 8192 + oc0 + ocg * 8;
                const float* ap = sm + OFF_ACT2 + p * 28 + iy * 5 + kx;
                #pragma unroll 4
                for (int ic = 0; ic < 64; ic++) {
                    ulonglong2 wA = *(const ulonglong2*)(wb + ic * 128);
                    ulonglong2 wB = *(const ulonglong2*)(wb + ic * 128 + 4);
                    float a0 = ap[ic * 224];                 /* px = 2*pxh+0 */
                    u64 aa0 = pack2(a0, a0);
                    fma2(acc[0][0], aa0, wA.x); fma2(acc[0][1], aa0, wA.y);
                    fma2(acc[0][2], aa0, wB.x); fma2(acc[0][3], aa0, wB.y);
                    if (kx < 2) {                            /* ix=2+kx<4: compile-time */
                        float a1 = ap[ic * 224 + 2];         /* px = 2*pxh+1 */
                        u64 aa1 = pack2(a1, a1);
                        fma2(acc[1][0], aa1, wA.x); fma2(acc[1][1], aa1, wA.y);
                        fma2(acc[1][2], aa1, wB.x); fma2(acc[1][3], aa1, wB.y);
                    }
                }
            }
        }
        #pragma unroll
        for (int i = 0; i < 2; i++) {
            int px = 2 * pxh + i;
            #pragma unroll
            for (int j = 0; j < 4; j++) {
                int oc = oc0 + ocg * 8 + 2 * j;
                float lo, hi; unpack2(acc[i][j], lo, hi);
                float* o = sm + OFF_ACT3 + p * 516 + px * 129 + oc;
                o[0] = fmaxf(lo + s_b[96 + oc], 0.f);
                o[1] = fmaxf(hi + s_b[96 + oc + 1], 0.f);
            }
        }
    }
    __syncthreads();

    /* ---- dense 512->64: warp=oc-group(8), lanes=(kq,p); butterfly K-reduce ---- */
    {
        const int oc0 = wid * 8;
        const int kq = lane >> 3, pl = lane & 7;
        u64 acc[4] = {0ull, 0ull, 0ull, 0ull};

        #pragma unroll 1
        for (int s = 0; s < 2; s++) {
            __syncthreads();
            #pragma unroll
            for (int j = 0; j < 16; j++) {
                int idx = tid + j * 256;
                int row = idx >> 4;
                int col = (idx & 15) * 4;
                int kqs = row >> 6, rr = row & 63;
                cp16(sm + OFF_ACT1 + kqs * 4104 + rr * 64 + col,
                     wd + (kqs * 128 + s * 64 + rr) * 64 + col);
            }
            cp_commit();
            cp_wait0();
            __syncthreads();

            const float* xp = sm + OFF_ACT3 + pl * 516 + kq * 129 + s * 64;
            const float* wp = sm + OFF_ACT1 + kq * 4104 + oc0;
            #pragma unroll 8
            for (int kk = 0; kk < 64; kk++) {
                float x = xp[kk];
                u64 xx = pack2(x, x);
                ulonglong2 w01 = *(const ulonglong2*)(wp + kk * 64);
                ulonglong2 w23 = *(const ulonglong2*)(wp + kk * 64 + 4);
                fma2(acc[0], xx, w01.x); fma2(acc[1], xx, w01.y);
                fma2(acc[2], xx, w23.x); fma2(acc[3], xx, w23.y);
            }
        }
        float r[8];
        #pragma unroll
        for (int j = 0; j < 4; j++) unpack2(acc[j], r[2 * j], r[2 * j + 1]);
        #pragma unroll
        for (int j = 0; j < 8; j++) {
            r[j] += __shfl_xor_sync(0xffffffffu, r[j], 8);
            r[j] += __shfl_xor_sync(0xffffffffu, r[j], 16);
        }
        if (kq == 0) {
            #pragma unroll
            for (int j = 0; j < 8; j++) {
                int e = oc0 + j;
                sm[OFF_V + pl * 64 + e] = r[j] + s_b[224 + e];
            }
        }
    }
    __syncthreads();

    /* ---- head: vn2, stage c_x (stride 65), d2 -> ow -> atomics ---- */
    if (tid < GP) {
        float a = 0.f;
        const float* vp = sm + OFF_V + tid * 64;
        #pragma unroll 8
        for (int e = 0; e < 64; e++) a = fmaf(vp[e], vp[e], a);
        sm[OFF_VN2 + tid] = a;
    }
    for (int i = tid; i < 8192; i += T) {
        int k = i >> 6, e = i & 63;
        sm[OFF_ACT1 + k * 65 + e] = c_x[i];
    }
    __syncthreads();

    {
        float inv_s2 = 1.f / (sigma[0] * sigma[0]);
        int k = tid & 127, pg = tid >> 7;
        u64 d01 = pack2(sm[OFF_VN2 + pg * 4],     sm[OFF_VN2 + pg * 4 + 1]);
        u64 d23 = pack2(sm[OFF_VN2 + pg * 4 + 2], sm[OFF_VN2 + pg * 4 + 3]);
        const u64 neg2 = pack2(-2.f, -2.f);
        const float* vp = sm + OFF_V + pg * 256;
        const float* ck = sm + OFF_ACT1 + k * 65;
        #pragma unroll 8
        for (int e = 0; e < 64; e++) {
            float cv = ck[e];
            u64 cc = pack2(cv, cv);
            u64 v01 = pack2(vp[e],       vp[64 + e]);
            u64 v23 = pack2(vp[128 + e], vp[192 + e]);
            u64 t01 = cc, t23 = cc;
            fma2(t01, neg2, v01);
            fma2(t23, neg2, v23);
            fma2(d01, cc, t01);
            fma2(d23, cc, t23);
        }
        float d[4];
        unpack2(d01, d[0], d[1]);
        unpack2(d23, d[2], d[3]);
        int b0 = (g0 + pg * 4)     / NPP;
        int b3 = (g0 + pg * 4 + 3) / NPP;
        float accA = 0.f, accB = 0.f;
        float cwk = s_cw[k];
        #pragma unroll
        for (int pp = 0; pp < 4; pp++) {
            float dd = fmaxf(d[pp], 0.f);
            float owv = fmaxf(cwk * expf(-dd * inv_s2), 1e-10f);
            int b = (g0 + pg * 4 + pp) / NPP;
            if (b == b0) accA += owv; else accB += owv;
        }
        atomicAdd(&g_ysum[b0 * 128 + k], accA);
        if (b3 != b0) atomicAdd(&g_ysum[b3 * 128 + k], accB);
    }

    /* ---- last-CTA finalize ---- */
    __syncthreads();
    __shared__ unsigned s_rank;
    if (tid == 0) {
        __threadfence();
        s_rank = atomicAdd(&g_count, 1u);
    }
    __syncthreads();
    if (s_rank == NBLK - 1) {
        __threadfence();
        float* s_y   = sm + OFF_RS;
        float* yv2   = s_y + 2048;
        float* rsum  = yv2 + 1280;
        for (int i = tid; i < NB * 128; i += T) {
            s_y[i] = g_ysum[i];
            g_ysum[i] = 0.f;
        }
        if (tid == 0) g_count = 0u;
        __syncthreads();
        for (int k = tid; k < 128; k += T) {
            float n2 = 0.f;
            #pragma unroll
            for (int i = 0; i < 10; i++) { float c = c_y[k * 10 + i]; n2 = fmaf(c, c, n2); }
            float inv = 1.f / n2;
            #pragma unroll
            for (int i = 0; i < 10; i++) { float c = c_y[k * 10 + i]; yv2[k * 10 + i] = c * c * inv; }
        }
        if (tid < NB) {
            float s = 0.f;
            for (int k = 0; k < 128; k++) s += s_y[tid * 128 + k];
            rsum[tid] = s;
        }
        __syncthreads();
        if (tid < NB * 10) {
            int b = tid / 10, i = tid % 10;
            float a = 0.f;
            for (int k = 0; k < 128; k++) a = fmaf(s_y[b * 128 + k], yv2[k * 10 + i], a);
            out[tid] = a / rsum[b];
        }
    }
}

extern "C" void kernel_launch(void* const* d_in, const int* in_sizes, int n_in,
                              void* d_out, int out_size) {
    (void)in_sizes; (void)n_in; (void)out_size;
    const float* images = (const float*)d_in[0];
    const float* w1     = (const float*)d_in[1];
    const float* b1     = (const float*)d_in[2];
    const float* w2     = (const float*)d_in[3];
    const float* b2     = (const float*)d_in[4];
    const float* w3     = (const float*)d_in[5];
    const float* b3     = (const float*)d_in[6];
    const float* wd     = (const float*)d_in[7];
    const float* bd     = (const float*)d_in[8];
    const float* c_x    = (const float*)d_in[9];
    const float* c_y    = (const float*)d_in[10];
    const float* comp_w = (const float*)d_in[11];
    const float* sigma  = (const float*)d_in[12];
    float* out = (float*)d_out;

    cudaFuncSetAttribute(main_kernel, cudaFuncAttributeMaxDynamicSharedMemorySize, SMEM_BYTES);

    main_kernel<<<NBLK, T, SMEM_BYTES>>>(images, w1, b1, w2, b2, w3, b3,
                                         wd, bd, c_x, c_y, comp_w, sigma, out);
}

// round 9
// speedup vs baseline: 1.7234x; 1.0083x over previous
#include <cuda_runtime.h>
#include <math.h>

typedef unsigned long long u64;

#define T 256
#define GP 8
#define NB   16
#define NPQ  45
#define NPP  (NPQ*NPQ)
#define NTOT (NB*NPP)
#define NBLK (NTOT/GP)      /* 4050 CTAs */

/* float offsets in dynamic smem */
#define OFF_RS    0         /* 6936  : resized planar [3][8p][289] (17x17)       */
#define OFF_ACT1  6936      /* 24192 : [32ic][9iy][84] (p*9+ix); reused w3/wd/cx */
#define OFF_ACT2  31128     /* 14336 : [64ic][8p][28] (5x5 in 28-stride, pad 0)  */
#define OFF_ACT3  45464     /* 4128  : [8p][516] (px*129+oc)                     */
#define OFF_RAW   49592     /* 1536  : [3][8p][64]                               */
#define OFF_W2S   51128     /* 4096  : w2 tap double buffer                      */
#define OFF_W1    55224     /* 864                                               */
#define OFF_V     56088     /* 512   : [p][64]                                   */
#define OFF_B     56600     /* 288   : b1 b2 b3 bd                               */
#define OFF_CW    56888     /* 128                                               */
#define OFF_VN2   57016     /* 8                                                 */
#define SMEM_FLOATS 57024
#define SMEM_BYTES  (SMEM_FLOATS * 4)

__device__ float    g_ysum[NB * 128];
__device__ unsigned g_count;

/* ---- packed fp32x2 ---- */
__device__ __forceinline__ u64 pack2(float lo, float hi) {
    u64 r; asm("mov.b64 %0, {%1, %2};" : "=l"(r) : "f"(lo), "f"(hi)); return r;
}
__device__ __forceinline__ void unpack2(u64 v, float& lo, float& hi) {
    asm("mov.b64 {%0, %1}, %2;" : "=f"(lo), "=f"(hi) : "l"(v));
}
__device__ __forceinline__ void fma2(u64& d, u64 a, u64 b) {
    asm("fma.rn.f32x2 %0, %1, %2, %0;" : "+l"(d) : "l"(a), "l"(b));
}

__device__ __forceinline__ void cp16(float* dst, const float* src) {
    unsigned s = (unsigned)__cvta_generic_to_shared(dst);
    asm volatile("cp.async.cg.shared.global [%0], [%1], 16;\n" :: "r"(s), "l"(src));
}
__device__ __forceinline__ void cp_commit() { asm volatile("cp.async.commit_group;\n"); }
__device__ __forceinline__ void cp_wait0()  { asm volatile("cp.async.wait_group 0;\n"); }

/* jax.image.resize 'linear' 8->16 */
__device__ __forceinline__ void rtab(int i, int& a0, int& a1, float& w0, float& w1) {
    if (i == 0)       { a0 = 0; a1 = 0; w0 = 1.f;   w1 = 0.f;   }
    else if (i == 15) { a0 = 7; a1 = 7; w0 = 1.f;   w1 = 0.f;   }
    else if (i & 1)   { int m = i >> 1; a0 = m;     a1 = m + 1; w0 = 0.75f; w1 = 0.25f; }
    else              { int m = i >> 1; a0 = m - 1; a1 = m;     w0 = 0.25f; w1 = 0.75f; }
}

__global__ __launch_bounds__(T, 1)
void main_kernel(const float* __restrict__ images,
                 const float* __restrict__ w1, const float* __restrict__ b1,
                 const float* __restrict__ w2, const float* __restrict__ b2,
                 const float* __restrict__ w3, const float* __restrict__ b3,
                 const float* __restrict__ wd, const float* __restrict__ bd,
                 const float* __restrict__ c_x, const float* __restrict__ c_y,
                 const float* __restrict__ comp_w, const float* __restrict__ sigma,
                 float* __restrict__ out)
{
    extern __shared__ float sm[];
    const int tid  = threadIdx.x;
    const int g0   = blockIdx.x * GP;
    const int wid  = tid >> 5;
    const int lane = tid & 31;

    float* s_b  = sm + OFF_B;
    float* s_cw = sm + OFF_CW;

    /* ---- init ---- */
    for (int i = tid; i < 864; i += T) sm[OFF_W1 + i] = w1[i];
    if (tid < 32)  s_b[tid]       = b1[tid];
    if (tid < 64)  s_b[32 + tid]  = b2[tid];
    if (tid < 128) s_b[96 + tid]  = b3[tid];
    if (tid < 64)  s_b[224 + tid] = bd[tid];
    if (tid < 128) s_cw[tid]      = comp_w[tid];
    for (int i = tid; i < OFF_RAW / 4; i += T)          /* zero rs+act1+act2+act3 */
        ((float4*)sm)[i] = make_float4(0.f, 0.f, 0.f, 0.f);

    for (int i = tid; i < 1536; i += T) {
        int c = i >> 9, rem = i & 511, p = rem >> 6, r = rem & 63;
        int iy = r >> 3, ix = r & 7;
        int g = g0 + p, b = g / NPP, pp = g % NPP;
        int py = pp / NPQ, px = pp % NPQ;
        sm[OFF_RAW + i] = images[((b * 96 + py * 2 + iy) * 96 + px * 2 + ix) * 3 + c];
    }
    __syncthreads();

    /* ---- resize 8x8 -> 16x16 into padded 17x17 planes ---- */
    for (int i = tid; i < 6144; i += T) {
        int c = i >> 11, rem = i & 2047, p = rem >> 8, r = rem & 255;
        int oy = r >> 4, ox = r & 15;
        int ay0, ay1, ax0, ax1; float wy0, wy1, wx0, wx1;
        rtab(oy, ay0, ay1, wy0, wy1);
        rtab(ox, ax0, ax1, wx0, wx1);
        const float* rp = sm + OFF_RAW + c * 512 + p * 64;
        float v00 = rp[ay0 * 8 + ax0], v01 = rp[ay0 * 8 + ax1];
        float v10 = rp[ay1 * 8 + ax0], v11 = rp[ay1 * 8 + ax1];
        sm[OFF_RS + c * 2312 + p * 289 + oy * 17 + ox] =
            wy0 * (wx0 * v00 + wx1 * v01) + wy1 * (wx0 * v10 + wx1 * v11);
    }
    __syncthreads();

    /* ---- conv1: M=512 N=32 K=27, TM=8, TN=8; writes act1 [ic][iy*84 + p*9+ix] ---- */
    {
        const int mt = tid >> 2, ng = tid & 3;
        const int p = mt >> 3, oy = mt & 7;
        u64 acc[8][4];
        #pragma unroll
        for (int i = 0; i < 8; i++)
            #pragma unroll
            for (int j = 0; j < 4; j++) acc[i][j] = 0ull;

        #pragma unroll 1
        for (int ky = 0; ky < 3; ky++)
        #pragma unroll 1
        for (int kx = 0; kx < 3; kx++) {
            #pragma unroll
            for (int c = 0; c < 3; c++) {
                const float* ap = sm + OFF_RS + c * 2312 + p * 289 + (2 * oy + ky) * 17 + kx;
                u64 aa[8];
                #pragma unroll
                for (int ox = 0; ox < 8; ox++) { float av = ap[2 * ox]; aa[ox] = pack2(av, av); }
                const u64* wp2 = (const u64*)(sm + OFF_W1 + ((ky * 3 + kx) * 3 + c) * 32 + ng * 8);
                u64 bb[4] = {wp2[0], wp2[1], wp2[2], wp2[3]};
                #pragma unroll
                for (int ox = 0; ox < 8; ox++)
                    #pragma unroll
                    for (int j = 0; j < 4; j++)
                        fma2(acc[ox][j], aa[ox], bb[j]);
            }
        }
        #pragma unroll
        for (int j = 0; j < 4; j++) {
            int oc0 = ng * 8 + 2 * j;
            float bi0 = s_b[oc0], bi1 = s_b[oc0 + 1];
            float* op0 = sm + OFF_ACT1 + oc0 * 756 + oy * 84 + p * 9;
            float* op1 = op0 + 756;
            #pragma unroll
            for (int ox = 0; ox < 8; ox++) {
                float lo, hi; unpack2(acc[ox][j], lo, hi);
                op0[ox] = fmaxf(lo + bi0, 0.f);
                op1[ox] = fmaxf(hi + bi1, 0.f);
            }
        }
    }
    __syncthreads();

    /* ---- conv2: warp = (m-half, oc-quad); lane = (oc-octet, pix) so weight
           LDS carries 2 distinct addresses (full rows, not broadcast) ---- */
    {
        const int mh  = wid >> 2;          /* p-half: p in {mh*4 .. mh*4+3} */
        const int ocq = wid & 3;
        const int ocg = lane & 1;
        const int pix = lane >> 1;         /* 16: (oy, ox) */
        const int oy = pix >> 2, ox = pix & 3;
        const int oc0 = ocq * 16 + ocg * 8;
        u64 acc[4][4];
        #pragma unroll
        for (int i = 0; i < 4; i++)
            #pragma unroll
            for (int j = 0; j < 4; j++) acc[i][j] = 0ull;

        #pragma unroll
        for (int j = 0; j < 2; j++) {
            int i4 = tid + j * 256;
            cp16(sm + OFF_W2S + i4 * 4, w2 + i4 * 4);
        }
        cp_commit();

        #pragma unroll 1
        for (int t = 0; t < 9; t++) {
            cp_wait0();
            __syncthreads();
            if (t < 8) {
                #pragma unroll
                for (int j = 0; j < 2; j++) {
                    int i4 = tid + j * 256;
                    cp16(sm + OFF_W2S + ((t + 1) & 1) * 2048 + i4 * 4,
                         w2 + (t + 1) * 2048 + i4 * 4);
                }
                cp_commit();
            }
            int ky = t / 3, kx = t - ky * 3;
            const float* ab = sm + OFF_ACT1 + (2 * oy + ky) * 84 + (mh * 4) * 9 + (2 * ox + kx);
            const float* wb = sm + OFF_W2S + (t & 1) * 2048 + oc0;
            #pragma unroll 8
            for (int ic = 0; ic < 32; ic++) {
                ulonglong2 wA = *(const ulonglong2*)(wb + ic * 64);       /* 2 distinct/instr */
                ulonglong2 wB = *(const ulonglong2*)(wb + ic * 64 + 4);
                const float* ai = ab + ic * 756;
                #pragma unroll
                for (int i = 0; i < 4; i++) {
                    float av = ai[9 * i];
                    u64 aa = pack2(av, av);
                    fma2(acc[i][0], aa, wA.x);
                    fma2(acc[i][1], aa, wA.y);
                    fma2(acc[i][2], aa, wB.x);
                    fma2(acc[i][3], aa, wB.y);
                }
            }
        }
        #pragma unroll
        for (int j = 0; j < 4; j++) {
            int oc = oc0 + 2 * j;
            float bi0 = s_b[32 + oc], bi1 = s_b[32 + oc + 1];
            #pragma unroll
            for (int i = 0; i < 4; i++) {
                int p = mh * 4 + i;
                float lo, hi; unpack2(acc[i][j], lo, hi);
                float* o = sm + OFF_ACT2 + oc * 224 + p * 28 + oy * 5 + ox;
                o[0]   = fmaxf(lo + bi0, 0.f);
                o[224] = fmaxf(hi + bi1, 0.f);
            }
        }
    }
    __syncthreads();

    /* ---- conv3: warp = 16 oc; lane = (m-pair, oc-octet), 2-addr weight loads ---- */
    {
        const int oc0 = wid * 16;
        const int ocg = lane & 1;
        const int mgp = lane >> 1;
        const int p   = mgp >> 1;
        const int pxh = mgp & 1;
        u64 acc[2][4];
        #pragma unroll
        for (int i = 0; i < 2; i++)
            #pragma unroll
            for (int j = 0; j < 4; j++) acc[i][j] = 0ull;

        #pragma unroll
        for (int j = 0; j < 8; j++) {
            int i4 = tid + j * 256;
            cp16(sm + OFF_ACT1 + i4 * 4, w3 + i4 * 4);
        }
        cp_commit();

        #pragma unroll 1
        for (int t = 0; t < 9; t++) {
            cp_wait0();
            __syncthreads();
            if (t < 8) {
                #pragma unroll
                for (int j = 0; j < 8; j++) {
                    int i4 = tid + j * 256;
                    cp16(sm + OFF_ACT1 + ((t + 1) & 1) * 8192 + i4 * 4,
                         w3 + (t + 1) * 8192 + i4 * 4);
                }
                cp_commit();
            }
            int ky = t / 3, kx = t - (t / 3) * 3;
            const int iy = 2 * pxh + ky;
            if (iy < 4) {
                const float* wb = sm + OFF_ACT1 + (t & 1) * 8192 + oc0 + ocg * 8;
                const float* ap = sm + OFF_ACT2 + p * 28 + iy * 5 + kx;
                #pragma unroll 4
                for (int ic = 0; ic < 64; ic++) {
                    ulonglong2 wA = *(const ulonglong2*)(wb + ic * 128);
                    ulonglong2 wB = *(const ulonglong2*)(wb + ic * 128 + 4);
                    float a0 = ap[ic * 224];
                    u64 aa0 = pack2(a0, a0);
                    fma2(acc[0][0], aa0, wA.x); fma2(acc[0][1], aa0, wA.y);
                    fma2(acc[0][2], aa0, wB.x); fma2(acc[0][3], aa0, wB.y);
                    if (kx < 2) {
                        float a1 = ap[ic * 224 + 2];
                        u64 aa1 = pack2(a1, a1);
                        fma2(acc[1][0], aa1, wA.x); fma2(acc[1][1], aa1, wA.y);
                        fma2(acc[1][2], aa1, wB.x); fma2(acc[1][3], aa1, wB.y);
                    }
                }
            }
        }
        #pragma unroll
        for (int i = 0; i < 2; i++) {
            int px = 2 * pxh + i;
            #pragma unroll
            for (int j = 0; j < 4; j++) {
                int oc = oc0 + ocg * 8 + 2 * j;
                float lo, hi; unpack2(acc[i][j], lo, hi);
                float* o = sm + OFF_ACT3 + p * 516 + px * 129 + oc;
                o[0] = fmaxf(lo + s_b[96 + oc], 0.f);
                o[1] = fmaxf(hi + s_b[96 + oc + 1], 0.f);
            }
        }
    }
    __syncthreads();

    /* ---- dense 512->64: warp=oc-group(8), lanes=(kq,p); butterfly K-reduce ---- */
    {
        const int oc0 = wid * 8;
        const int kq = lane >> 3, pl = lane & 7;
        u64 acc[4] = {0ull, 0ull, 0ull, 0ull};

        #pragma unroll 1
        for (int s = 0; s < 2; s++) {
            __syncthreads();
            #pragma unroll
            for (int j = 0; j < 16; j++) {
                int idx = tid + j * 256;
                int row = idx >> 4;
                int col = (idx & 15) * 4;
                int kqs = row >> 6, rr = row & 63;
                cp16(sm + OFF_ACT1 + kqs * 4104 + rr * 64 + col,
                     wd + (kqs * 128 + s * 64 + rr) * 64 + col);
            }
            cp_commit();
            cp_wait0();
            __syncthreads();

            const float* xp = sm + OFF_ACT3 + pl * 516 + kq * 129 + s * 64;
            const float* wp = sm + OFF_ACT1 + kq * 4104 + oc0;
            #pragma unroll 8
            for (int kk = 0; kk < 64; kk++) {
                float x = xp[kk];
                u64 xx = pack2(x, x);
                ulonglong2 w01 = *(const ulonglong2*)(wp + kk * 64);
                ulonglong2 w23 = *(const ulonglong2*)(wp + kk * 64 + 4);
                fma2(acc[0], xx, w01.x); fma2(acc[1], xx, w01.y);
                fma2(acc[2], xx, w23.x); fma2(acc[3], xx, w23.y);
            }
        }
        float r[8];
        #pragma unroll
        for (int j = 0; j < 4; j++) unpack2(acc[j], r[2 * j], r[2 * j + 1]);
        #pragma unroll
        for (int j = 0; j < 8; j++) {
            r[j] += __shfl_xor_sync(0xffffffffu, r[j], 8);
            r[j] += __shfl_xor_sync(0xffffffffu, r[j], 16);
        }
        if (kq == 0) {
            #pragma unroll
            for (int j = 0; j < 8; j++) {
                int e = oc0 + j;
                sm[OFF_V + pl * 64 + e] = r[j] + s_b[224 + e];
            }
        }
    }
    __syncthreads();

    /* ---- head: vn2, stage c_x (stride 65), d2 -> ow -> atomics ---- */
    if (tid < GP) {
        float a = 0.f;
        const float* vp = sm + OFF_V + tid * 64;
        #pragma unroll 8
        for (int e = 0; e < 64; e++) a = fmaf(vp[e], vp[e], a);
        sm[OFF_VN2 + tid] = a;
    }
    for (int i = tid; i < 8192; i += T) {
        int k = i >> 6, e = i & 63;
        sm[OFF_ACT1 + k * 65 + e] = c_x[i];
    }
    __syncthreads();

    {
        float inv_s2 = 1.f / (sigma[0] * sigma[0]);
        int k = tid & 127, pg = tid >> 7;
        u64 d01 = pack2(sm[OFF_VN2 + pg * 4],     sm[OFF_VN2 + pg * 4 + 1]);
        u64 d23 = pack2(sm[OFF_VN2 + pg * 4 + 2], sm[OFF_VN2 + pg * 4 + 3]);
        const u64 neg2 = pack2(-2.f, -2.f);
        const float* vp = sm + OFF_V + pg * 256;
        const float* ck = sm + OFF_ACT1 + k * 65;
        #pragma unroll 8
        for (int e = 0; e < 64; e++) {
            float cv = ck[e];
            u64 cc = pack2(cv, cv);
            u64 v01 = pack2(vp[e],       vp[64 + e]);
            u64 v23 = pack2(vp[128 + e], vp[192 + e]);
            u64 t01 = cc, t23 = cc;
            fma2(t01, neg2, v01);
            fma2(t23, neg2, v23);
            fma2(d01, cc, t01);
            fma2(d23, cc, t23);
        }
        float d[4];
        unpack2(d01, d[0], d[1]);
        unpack2(d23, d[2], d[3]);
        int b0 = (g0 + pg * 4)     / NPP;
        int b3 = (g0 + pg * 4 + 3) / NPP;
        float accA = 0.f, accB = 0.f;
        float cwk = s_cw[k];
        #pragma unroll
        for (int pp = 0; pp < 4; pp++) {
            float dd = fmaxf(d[pp], 0.f);
            float owv = fmaxf(cwk * expf(-dd * inv_s2), 1e-10f);
            int b = (g0 + pg * 4 + pp) / NPP;
            if (b == b0) accA += owv; else accB += owv;
        }
        atomicAdd(&g_ysum[b0 * 128 + k], accA);
        if (b3 != b0) atomicAdd(&g_ysum[b3 * 128 + k], accB);
    }

    /* ---- last-CTA finalize ---- */
    __syncthreads();
    __shared__ unsigned s_rank;
    if (tid == 0) {
        __threadfence();
        s_rank = atomicAdd(&g_count, 1u);
    }
    __syncthreads();
    if (s_rank == NBLK - 1) {
        __threadfence();
        float* s_y   = sm + OFF_RS;
        float* yv2   = s_y + 2048;
        float* rsum  = yv2 + 1280;
        for (int i = tid; i < NB * 128; i += T) {
            s_y[i] = g_ysum[i];
            g_ysum[i] = 0.f;
        }
        if (tid == 0) g_count = 0u;
        __syncthreads();
        for (int k = tid; k < 128; k += T) {
            float n2 = 0.f;
            #pragma unroll
            for (int i = 0; i < 10; i++) { float c = c_y[k * 10 + i]; n2 = fmaf(c, c, n2); }
            float inv = 1.f / n2;
            #pragma unroll
            for (int i = 0; i < 10; i++) { float c = c_y[k * 10 + i]; yv2[k * 10 + i] = c * c * inv; }
        }
        if (tid < NB) {
            float s = 0.f;
            for (int k = 0; k < 128; k++) s += s_y[tid * 128 + k];
            rsum[tid] = s;
        }
        __syncthreads();
        if (tid < NB * 10) {
            int b = tid / 10, i = tid % 10;
            float a = 0.f;
            for (int k = 0; k < 128; k++) a = fmaf(s_y[b * 128 + k], yv2[k * 10 + i], a);
            out[tid] = a / rsum[b];
        }
    }
}

extern "C" void kernel_launch(void* const* d_in, const int* in_sizes, int n_in,
                              void* d_out, int out_size) {
    (void)in_sizes; (void)n_in; (void)out_size;
    const float* images = (const float*)d_in[0];
    const float* w1     = (const float*)d_in[1];
    const float* b1     = (const float*)d_in[2];
    const float* w2     = (const float*)d_in[3];
    const float* b2     = (const float*)d_in[4];
    const float* w3     = (const float*)d_in[5];
    const float* b3     = (const float*)d_in[6];
    const float* wd     = (const float*)d_in[7];
    const float* bd     = (const float*)d_in[8];
    const float* c_x    = (const float*)d_in[9];
    const float* c_y    = (const float*)d_in[10];
    const float* comp_w = (const float*)d_in[11];
    const float* sigma  = (const float*)d_in[12];
    float* out = (float*)d_out;

    cudaFuncSetAttribute(main_kernel, cudaFuncAttributeMaxDynamicSharedMemorySize, SMEM_BYTES);

    main_kernel<<<NBLK, T, SMEM_BYTES>>>(images, w1, b1, w2, b2, w3, b3,
                                         wd, bd, c_x, c_y, comp_w, sigma, out);
}